// round 1
// baseline (speedup 1.0000x reference)
#include <cuda_runtime.h>
#include <math.h>

// Problem constants (match reference setup_inputs)
#define NSENT 64
#define S_LEN 512
#define D_DIM 768
#define NL    128
#define HID   512
#define CLS   3
#define E_MAX 2000
#define P_MAX 20000
#define L_SPAN 8

// ---------------- static device scratch (no allocation allowed) ----------------
__device__ float g_eemb  [E_MAX * D_DIM];
__device__ float g_Amat  [E_MAX * HID];
__device__ float g_Bmat  [E_MAX * HID];
__device__ float g_Cmat  [E_MAX * HID];
__device__ float g_x     [E_MAX * NL];
__device__ float g_sintra[E_MAX * NL];
__device__ float g_sinter[E_MAX * NL];
__device__ float g_cintra[E_MAX];
__device__ float g_cinter[E_MAX];
__device__ float g_Z     [E_MAX * 3 * NL];
__device__ float g_Wcat  [3 * NL * NL];
__device__ float g_losspart[4];

// ---------------- event extraction: masked mean of up to 8 tokens --------------
__global__ void extract_kernel(const float* __restrict__ sent,
                               const int* __restrict__ esent,
                               const int* __restrict__ estart,
                               const int* __restrict__ elen,
                               float* __restrict__ eemb,
                               int S, int D)
{
    int e = blockIdx.x;
    int len = elen[e] + 1;           // 1..8
    int st  = estart[e];
    int snt = esent[e];
    float inv = 1.0f / (float)len;
    const float* base = sent + (size_t)snt * S * D;
    for (int d = threadIdx.x; d < D; d += blockDim.x) {
        float s = 0.f;
        for (int o = 0; o < len; o++) {
            int idx = st + o; if (idx > S - 1) idx = S - 1;
            s += base[(size_t)idx * D + d];
        }
        eemb[(size_t)e * D + d] = s * inv;
    }
}

// ---------------- generic fp32 tiled SGEMM (row-major), optional relu ----------
// C[M,N] = A[M,K](lda) * B[K,N](ldb); 64x64x16 tiles, 4x4 per thread, 256 thr
template<bool RELU>
__global__ void sgemm_k(int M, int N, int K,
                        const float* __restrict__ A, int lda,
                        const float* __restrict__ B, int ldb,
                        float* __restrict__ C, int ldc)
{
    const int BM = 64, BN = 64, BK = 16, TM = 4, TN = 4;
    __shared__ float As[BK][BM];
    __shared__ float Bs[BK][BN];
    int brow = blockIdx.y * BM, bcol = blockIdx.x * BN;
    int tid = threadIdx.x;
    int tx = tid % 16, ty = tid / 16;
    float acc[TM][TN];
    #pragma unroll
    for (int i = 0; i < TM; i++)
        #pragma unroll
        for (int j = 0; j < TN; j++) acc[i][j] = 0.f;

    for (int k0 = 0; k0 < K; k0 += BK) {
        for (int i = tid; i < BM * BK; i += 256) {
            int r = i / BK, c = i % BK;
            float v = 0.f;
            if (brow + r < M) v = A[(size_t)(brow + r) * lda + k0 + c];
            As[c][r] = v;
        }
        for (int i = tid; i < BK * BN; i += 256) {
            int r = i / BN, c = i % BN;
            float v = 0.f;
            if (bcol + c < N) v = B[(size_t)(k0 + r) * ldb + bcol + c];
            Bs[r][c] = v;
        }
        __syncthreads();
        #pragma unroll
        for (int k = 0; k < BK; k++) {
            float av[TM], bv[TN];
            #pragma unroll
            for (int i = 0; i < TM; i++) av[i] = As[k][ty * TM + i];
            #pragma unroll
            for (int j = 0; j < TN; j++) bv[j] = Bs[k][tx * TN + j];
            #pragma unroll
            for (int i = 0; i < TM; i++)
                #pragma unroll
                for (int j = 0; j < TN; j++)
                    acc[i][j] = fmaf(av[i], bv[j], acc[i][j]);
        }
        __syncthreads();
    }
    #pragma unroll
    for (int i = 0; i < TM; i++) {
        int r = brow + ty * TM + i;
        if (r >= M) continue;
        #pragma unroll
        for (int j = 0; j < TN; j++) {
            int cc = bcol + tx * TN + j;
            if (cc < N) {
                float v = acc[i][j];
                if (RELU) v = fmaxf(v, 0.f);
                C[(size_t)r * ldc + cc] = v;
            }
        }
    }
}

// ---------------- stack [W_self; W_intra; W_inter] into 384x128 ---------------
__global__ void wcat_kernel(const float* __restrict__ Wself,
                            const float* __restrict__ Wintra,
                            const float* __restrict__ Winter,
                            float* __restrict__ Wcat)
{
    int i = blockIdx.x * blockDim.x + threadIdx.x;
    if (i >= 3 * NL * NL) return;
    int k = i / NL, d = i % NL;
    const float* src = (k < NL) ? Wself : ((k < 2 * NL) ? Wintra : Winter);
    Wcat[i] = src[(k % NL) * NL + d];
}

__global__ void zero_loss_kernel(float* lp) { if (threadIdx.x < 4) lp[threadIdx.x] = 0.f; }

__global__ void zero_seg_kernel(float* sintra, float* sinter,
                                float* cintra, float* cinter, int E)
{
    int i = blockIdx.x * blockDim.x + threadIdx.x;
    if (i < E * NL) { sintra[i] = 0.f; sinter[i] = 0.f; }
    if (i < E)      { cintra[i] = 0.f; cinter[i] = 0.f; }
}

// ---------------- per-pair: hidden, logits, CE, masks, segment atomics --------
__global__ void pair_kernel(const float* __restrict__ Am, const float* __restrict__ Bm,
                            const float* __restrict__ Cm, const float* __restrict__ x,
                            const float* __restrict__ b1, const float* __restrict__ W2,
                            const float* __restrict__ b2,
                            const int* __restrict__ pair1, const int* __restrict__ pair2,
                            const int* __restrict__ rtype, const int* __restrict__ targ,
                            float* sintra, float* sinter, float* cintra, float* cinter,
                            float* lossacc, float* logits_out, int P)
{
    __shared__ float b1s[HID];
    __shared__ float W2s[HID * CLS];
    __shared__ float b2s[CLS];
    __shared__ float ce_s[8];
    int tid = threadIdx.x;
    for (int i = tid; i < HID; i += 256) b1s[i] = b1[i];
    for (int i = tid; i < HID * CLS; i += 256) W2s[i] = W2[i];
    if (tid < CLS) b2s[tid] = b2[tid];
    __syncthreads();

    int warp = tid >> 5, lane = tid & 31;
    int p = blockIdx.x * 8 + warp;
    float ce = 0.f;
    if (p < P) {
        int p1 = pair1[p], p2 = pair2[p];
        const float* av  = Am + (size_t)p1 * HID;
        const float* bv2 = Bm + (size_t)p2 * HID;
        const float* c1  = Cm + (size_t)p1 * HID;
        const float* c2  = Cm + (size_t)p2 * HID;
        float a0 = 0.f, a1 = 0.f, a2 = 0.f;
        #pragma unroll
        for (int j = 0; j < HID / 32; j++) {
            int idx = j * 32 + lane;
            float h = av[idx] + bv2[idx] + c1[idx] - c2[idx] + b1s[idx];
            h = fmaxf(h, 0.f);
            a0 = fmaf(h, W2s[idx * 3 + 0], a0);
            a1 = fmaf(h, W2s[idx * 3 + 1], a1);
            a2 = fmaf(h, W2s[idx * 3 + 2], a2);
        }
        #pragma unroll
        for (int o = 16; o; o >>= 1) {
            a0 += __shfl_xor_sync(0xffffffffu, a0, o);
            a1 += __shfl_xor_sync(0xffffffffu, a1, o);
            a2 += __shfl_xor_sync(0xffffffffu, a2, o);
        }
        float l0 = a0 + b2s[0], l1 = a1 + b2s[1], l2 = a2 + b2s[2];
        float m = fmaxf(l0, fmaxf(l1, l2));
        float s = expf(l0 - m) + expf(l1 - m) + expf(l2 - m);
        int tg = targ[p];
        float lt = (tg == 0) ? l0 : ((tg == 1) ? l1 : l2);
        ce = logf(s) + m - lt;              // -log_softmax[target]
        if (logits_out != nullptr && lane == 0) {
            logits_out[(size_t)p * 3 + 0] = l0;
            logits_out[(size_t)p * 3 + 1] = l1;
            logits_out[(size_t)p * 3 + 2] = l2;
        }
        int argm = 0; float mm = l0;
        if (l1 > mm) { mm = l1; argm = 1; }
        if (l2 > mm) { mm = l2; argm = 2; }
        bool conf = (1.0f / s) > 0.3f;      // p.max = exp(0)/s since mm==m
        int rt = rtype[p];
        if (conf && (argm == 1 || argm == 2)) {
            bool srcIs1 = (argm == 1);
            int src = srcIs1 ? p1 : p2;
            int dst = srcIs1 ? p2 : p1;
            float* sb = (rt == 0) ? sintra : sinter;
            float* cb = (rt == 0) ? cintra : cinter;
            #pragma unroll
            for (int j = 0; j < NL / 32; j++) {
                int d = j * 32 + lane;
                atomicAdd(&sb[(size_t)dst * NL + d], x[(size_t)src * NL + d]);
            }
            if (lane == 0) atomicAdd(&cb[dst], 1.0f);
        }
    }
    if (lane == 0) ce_s[warp] = (p < P) ? ce : 0.f;
    __syncthreads();
    if (tid == 0) {
        float t = ce_s[0] + ce_s[1] + ce_s[2] + ce_s[3]
                + ce_s[4] + ce_s[5] + ce_s[6] + ce_s[7];
        atomicAdd(lossacc, t);
    }
}

// ---------------- build Z = [x | 0.7*agg_intra | 0.3*agg_inter] ---------------
__global__ void zbuild_kernel(const float* __restrict__ x,
                              const float* __restrict__ sintra, const float* __restrict__ sinter,
                              const float* __restrict__ cintra, const float* __restrict__ cinter,
                              float* __restrict__ Z, int E)
{
    int i = blockIdx.x * blockDim.x + threadIdx.x;
    if (i >= E * 3 * NL) return;
    int e = i / (3 * NL), j = i % (3 * NL);
    float v;
    if (j < NL) {
        v = x[(size_t)e * NL + j];
    } else if (j < 2 * NL) {
        int d = j - NL;
        v = 0.7f * (sintra[(size_t)e * NL + d] + x[(size_t)e * NL + d]) / (cintra[e] + 1.0f);
    } else {
        int d = j - 2 * NL;
        v = 0.3f * sinter[(size_t)e * NL + d] / fmaxf(cinter[e], 1.0f);
    }
    Z[i] = v;
}

__global__ void final_loss_kernel(const float* lp, float* out, int P)
{
    out[0] = (lp[0] + lp[1] * 0.5f + lp[2] * (1.0f / 3.0f)) / (float)P;
}

// ---------------- launch ------------------------------------------------------
static inline dim3 gemm_grid(int M, int N) {
    return dim3((N + 63) / 64, (M + 63) / 64);
}

extern "C" void kernel_launch(void* const* d_in, const int* in_sizes, int n_in,
                              void* d_out, int out_size)
{
    const float* sent   = (const float*)d_in[0];
    const float* Wproj  = (const float*)d_in[1];
    const float* W1     = (const float*)d_in[2];
    const float* b1     = (const float*)d_in[3];
    const float* W2     = (const float*)d_in[4];
    const float* b2     = (const float*)d_in[5];
    const float* Wself  = (const float*)d_in[6];
    const float* Wintra = (const float*)d_in[7];
    const float* Winter = (const float*)d_in[8];
    const int* esent  = (const int*)d_in[9];
    const int* estart = (const int*)d_in[10];
    const int* elen   = (const int*)d_in[11];
    const int* pair1  = (const int*)d_in[12];
    const int* pair2  = (const int*)d_in[13];
    const int* rtype  = (const int*)d_in[14];
    const int* targ   = (const int*)d_in[15];
    float* out = (float*)d_out;

    int E = in_sizes[9];
    int P = in_sizes[12];
    if (E > E_MAX) E = E_MAX;
    if (P > P_MAX) P = P_MAX;

    float *eemb, *Am, *Bm, *Cm, *x, *sintra, *sinter, *cintra, *cinter, *Z, *Wcat, *lp;
    cudaGetSymbolAddress((void**)&eemb,   g_eemb);
    cudaGetSymbolAddress((void**)&Am,     g_Amat);
    cudaGetSymbolAddress((void**)&Bm,     g_Bmat);
    cudaGetSymbolAddress((void**)&Cm,     g_Cmat);
    cudaGetSymbolAddress((void**)&x,      g_x);
    cudaGetSymbolAddress((void**)&sintra, g_sintra);
    cudaGetSymbolAddress((void**)&sinter, g_sinter);
    cudaGetSymbolAddress((void**)&cintra, g_cintra);
    cudaGetSymbolAddress((void**)&cinter, g_cinter);
    cudaGetSymbolAddress((void**)&Z,      g_Z);
    cudaGetSymbolAddress((void**)&Wcat,   g_Wcat);
    cudaGetSymbolAddress((void**)&lp,     g_losspart);

    int loff = out_size - 3 * P;       // logits live at the tail; loss at [0]
    if (loff < 0) loff = 0;
    float* logits_out = out + loff;

    // 1) extract events
    extract_kernel<<<E, 256>>>(sent, esent, estart, elen, eemb, S_LEN, D_DIM);

    // 2) once-per-launch GEMMs: A = e@W1[0:768], B = e@W1[768:1536], x0 = e@Wproj
    sgemm_k<false><<<gemm_grid(E, HID), 256>>>(E, HID, D_DIM, eemb, D_DIM, W1,               HID, Am, HID);
    sgemm_k<false><<<gemm_grid(E, HID), 256>>>(E, HID, D_DIM, eemb, D_DIM, W1 + 768 * HID,   HID, Bm, HID);
    sgemm_k<false><<<gemm_grid(E, NL ), 256>>>(E, NL,  D_DIM, eemb, D_DIM, Wproj,            NL,  x,  NL);

    // 3) stacked update weights + loss accumulator reset
    wcat_kernel<<<(3 * NL * NL + 255) / 256, 256>>>(Wself, Wintra, Winter, Wcat);
    zero_loss_kernel<<<1, 32>>>(lp);

    // 4) three message-passing iterations
    for (int it = 0; it < 3; it++) {
        // C = x @ W1[1536:1664]
        sgemm_k<false><<<gemm_grid(E, HID), 256>>>(E, HID, NL, x, NL, W1 + 1536 * HID, HID, Cm, HID);
        zero_seg_kernel<<<(E * NL + 255) / 256, 256>>>(sintra, sinter, cintra, cinter, E);
        pair_kernel<<<(P + 7) / 8, 256>>>(Am, Bm, Cm, x, b1, W2, b2,
                                          pair1, pair2, rtype, targ,
                                          sintra, sinter, cintra, cinter,
                                          lp + it, (it == 2) ? logits_out : nullptr, P);
        zbuild_kernel<<<(E * 3 * NL + 255) / 256, 256>>>(x, sintra, sinter, cintra, cinter, Z, E);
        // x = relu(Z @ Wcat)
        sgemm_k<true><<<gemm_grid(E, NL), 256>>>(E, NL, 3 * NL, Z, 3 * NL, Wcat, NL, x, NL);
    }

    // 5) loss = sum_it ce_mean/(it+1)
    final_loss_kernel<<<1, 1>>>(lp, out, P);
}

// round 2
// speedup vs baseline: 2.4356x; 2.4356x over previous
#include <cuda_runtime.h>
#include <math.h>

#define NSENT 64
#define S_LEN 512
#define D_DIM 768
#define NL    128
#define HID   512
#define CLS   3
#define E_MAX 2000
#define P_MAX 20000
#define NBIG  1152            // 512(A) + 512(B) + 128(x)

// ---------------- static device scratch ----------------
__device__ float g_eemb [E_MAX * D_DIM];
__device__ float g_Wbig [D_DIM * NBIG];        // [W1a | W1b | Wproj] packed, row-major 768x1152
__device__ float g_ABX  [E_MAX * NBIG];        // [A | B | x] per event
__device__ float g_Cmat [E_MAX * HID];
__device__ float g_sintra[2][E_MAX * NL];
__device__ float g_sinter[2][E_MAX * NL];
__device__ float g_cintra[2][E_MAX];
__device__ float g_cinter[2][E_MAX];
__device__ float g_Z    [E_MAX * 3 * NL];
__device__ float g_Wcat [3 * NL * NL];
__device__ float g_losspart[4];

// ---------------- event extraction (float4) ----------------
__global__ void extract_kernel(const float* __restrict__ sent,
                               const int* __restrict__ esent,
                               const int* __restrict__ estart,
                               const int* __restrict__ elen,
                               float* __restrict__ eemb)
{
    int e = blockIdx.x;
    int len = elen[e] + 1;
    int st  = estart[e];
    int snt = esent[e];
    float inv = 1.0f / (float)len;
    const float4* base = (const float4*)(sent + (size_t)snt * S_LEN * D_DIM);
    int d4 = threadIdx.x;              // blockDim = 192 = 768/4
    float4 acc = make_float4(0.f, 0.f, 0.f, 0.f);
    for (int o = 0; o < len; o++) {
        int idx = st + o; if (idx > S_LEN - 1) idx = S_LEN - 1;
        float4 v = base[(size_t)idx * (D_DIM / 4) + d4];
        acc.x += v.x; acc.y += v.y; acc.z += v.z; acc.w += v.w;
    }
    acc.x *= inv; acc.y *= inv; acc.z *= inv; acc.w *= inv;
    ((float4*)(eemb + (size_t)e * D_DIM))[d4] = acc;
}

// ---------------- prep: pack Wbig, Wcat, zero phase-0 seg bufs + loss ----------
__global__ void prep_kernel(const float* __restrict__ W1,
                            const float* __restrict__ Wproj,
                            const float* __restrict__ Wself,
                            const float* __restrict__ Wintra,
                            const float* __restrict__ Winter,
                            int E)
{
    long i = (long)blockIdx.x * blockDim.x + threadIdx.x;
    const long N_WBIG = (long)D_DIM * NBIG;
    const long N_WCAT = 3 * NL * NL;
    if (i < N_WBIG) {
        int k = (int)(i / NBIG), n = (int)(i % NBIG);
        float v;
        if (n < 512)        v = W1[(size_t)k * HID + n];
        else if (n < 1024)  v = W1[(size_t)(768 + k) * HID + (n - 512)];
        else                v = Wproj[(size_t)k * NL + (n - 1024)];
        g_Wbig[i] = v;
        return;
    }
    i -= N_WBIG;
    if (i < N_WCAT) {
        int k = (int)(i / NL), d = (int)(i % NL);
        const float* src = (k < NL) ? Wself : ((k < 2 * NL) ? Wintra : Winter);
        g_Wcat[i] = src[(k % NL) * NL + d];
        return;
    }
    i -= N_WCAT;
    if (i < (long)E * NL) { g_sintra[0][i] = 0.f; g_sinter[0][i] = 0.f; return; }
    i -= (long)E * NL;
    if (i < E) { g_cintra[0][i] = 0.f; g_cinter[0][i] = 0.f; return; }
    i -= E;
    if (i < 4) g_losspart[i] = 0.f;
}

// ---------------- double-buffered float4 SGEMM ----------------
// requires: BM*(BK/4)==256, BK*(BN/4)==256, (BM/TM)*(BN/TN)==256,
//           K % BK == 0, N % BN == 0, lda/ldb/ldc % 4 == 0
template<int BM, int BN, int BK, int TM, int TN, bool RELU>
__global__ void __launch_bounds__(256) sgemm_t(
    int M, int N, int K,
    const float* __restrict__ A, int lda,
    const float* __restrict__ B, int ldb,
    float* __restrict__ C, int ldc)
{
    __shared__ float As[2][BK][BM];
    __shared__ float Bs[2][BK][BN];
    const int tid  = threadIdx.x;
    const int brow = blockIdx.y * BM;
    const int bcol = blockIdx.x * BN;

    const int AKV = BK / 4;
    const int ar  = tid / AKV;
    const int ac  = (tid % AKV) * 4;
    const int BNV = BN / 4;
    const int br  = tid / BNV;
    const int bc  = (tid % BNV) * 4;

    const int tx = tid % (BN / TN);
    const int ty = tid / (BN / TN);

    float4 areg, breg;
    // preload tile 0
    areg = make_float4(0.f, 0.f, 0.f, 0.f);
    if (brow + ar < M)
        areg = *(const float4*)(A + (size_t)(brow + ar) * lda + ac);
    breg = *(const float4*)(B + (size_t)br * ldb + bcol + bc);
    As[0][ac + 0][ar] = areg.x; As[0][ac + 1][ar] = areg.y;
    As[0][ac + 2][ar] = areg.z; As[0][ac + 3][ar] = areg.w;
    *(float4*)&Bs[0][br][bc] = breg;
    __syncthreads();

    float acc[TM][TN];
    #pragma unroll
    for (int i = 0; i < TM; i++)
        #pragma unroll
        for (int j = 0; j < TN; j++) acc[i][j] = 0.f;

    int buf = 0;
    for (int k0 = BK; k0 < K; k0 += BK) {
        // prefetch next tile (latency overlapped with compute below)
        areg = make_float4(0.f, 0.f, 0.f, 0.f);
        if (brow + ar < M)
            areg = *(const float4*)(A + (size_t)(brow + ar) * lda + k0 + ac);
        breg = *(const float4*)(B + (size_t)(k0 + br) * ldb + bcol + bc);

        #pragma unroll
        for (int k = 0; k < BK; k++) {
            float av[TM], bv[TN];
            #pragma unroll
            for (int v = 0; v < TM / 4; v++)
                *(float4*)&av[v * 4] = *(const float4*)&As[buf][k][ty * TM + v * 4];
            #pragma unroll
            for (int v = 0; v < TN / 4; v++)
                *(float4*)&bv[v * 4] = *(const float4*)&Bs[buf][k][tx * TN + v * 4];
            #pragma unroll
            for (int i = 0; i < TM; i++)
                #pragma unroll
                for (int j = 0; j < TN; j++)
                    acc[i][j] = fmaf(av[i], bv[j], acc[i][j]);
        }

        As[buf ^ 1][ac + 0][ar] = areg.x; As[buf ^ 1][ac + 1][ar] = areg.y;
        As[buf ^ 1][ac + 2][ar] = areg.z; As[buf ^ 1][ac + 3][ar] = areg.w;
        *(float4*)&Bs[buf ^ 1][br][bc] = breg;
        __syncthreads();
        buf ^= 1;
    }
    // last tile
    #pragma unroll
    for (int k = 0; k < BK; k++) {
        float av[TM], bv[TN];
        #pragma unroll
        for (int v = 0; v < TM / 4; v++)
            *(float4*)&av[v * 4] = *(const float4*)&As[buf][k][ty * TM + v * 4];
        #pragma unroll
        for (int v = 0; v < TN / 4; v++)
            *(float4*)&bv[v * 4] = *(const float4*)&Bs[buf][k][tx * TN + v * 4];
        #pragma unroll
        for (int i = 0; i < TM; i++)
            #pragma unroll
            for (int j = 0; j < TN; j++)
                acc[i][j] = fmaf(av[i], bv[j], acc[i][j]);
    }

    // store (N exact multiple of BN; only M guarded)
    #pragma unroll
    for (int i = 0; i < TM; i++) {
        int r = brow + ty * TM + i;
        if (r >= M) continue;
        #pragma unroll
        for (int v = 0; v < TN / 4; v++) {
            float4 o;
            o.x = acc[i][v * 4 + 0]; o.y = acc[i][v * 4 + 1];
            o.z = acc[i][v * 4 + 2]; o.w = acc[i][v * 4 + 3];
            if (RELU) {
                o.x = fmaxf(o.x, 0.f); o.y = fmaxf(o.y, 0.f);
                o.z = fmaxf(o.z, 0.f); o.w = fmaxf(o.w, 0.f);
            }
            *(float4*)(C + (size_t)r * ldc + bcol + tx * TN + v * 4) = o;
        }
    }
}

// ---------------- per-pair: logits, CE, masks, segment atomics ----------------
__global__ void pair_kernel(const float* __restrict__ ABX,  // lda NBIG: A|B|x
                            const float* __restrict__ Cm,   // lda HID
                            const float* __restrict__ b1, const float* __restrict__ W2,
                            const float* __restrict__ b2,
                            const int* __restrict__ pair1, const int* __restrict__ pair2,
                            const int* __restrict__ rtype, const int* __restrict__ targ,
                            float* sintra, float* sinter, float* cintra, float* cinter,
                            float* lossacc, float* logits_out, int P)
{
    __shared__ float b1s[HID];
    __shared__ float W2s[HID * CLS];
    __shared__ float b2s[CLS];
    __shared__ float ce_s[8];
    int tid = threadIdx.x;
    for (int i = tid; i < HID; i += 256) b1s[i] = b1[i];
    for (int i = tid; i < HID * CLS; i += 256) W2s[i] = W2[i];
    if (tid < CLS) b2s[tid] = b2[tid];
    __syncthreads();

    int warp = tid >> 5, lane = tid & 31;
    int p = blockIdx.x * 8 + warp;
    float ce = 0.f;
    if (p < P) {
        int p1 = pair1[p], p2 = pair2[p];
        const float* av  = ABX + (size_t)p1 * NBIG;           // A[p1]
        const float* bv2 = ABX + (size_t)p2 * NBIG + 512;     // B[p2]
        const float* c1  = Cm + (size_t)p1 * HID;
        const float* c2  = Cm + (size_t)p2 * HID;
        float a0 = 0.f, a1 = 0.f, a2 = 0.f;
        #pragma unroll
        for (int j = 0; j < HID / 32; j++) {
            int idx = j * 32 + lane;
            float h = av[idx] + bv2[idx] + c1[idx] - c2[idx] + b1s[idx];
            h = fmaxf(h, 0.f);
            a0 = fmaf(h, W2s[idx * 3 + 0], a0);
            a1 = fmaf(h, W2s[idx * 3 + 1], a1);
            a2 = fmaf(h, W2s[idx * 3 + 2], a2);
        }
        #pragma unroll
        for (int o = 16; o; o >>= 1) {
            a0 += __shfl_xor_sync(0xffffffffu, a0, o);
            a1 += __shfl_xor_sync(0xffffffffu, a1, o);
            a2 += __shfl_xor_sync(0xffffffffu, a2, o);
        }
        float l0 = a0 + b2s[0], l1 = a1 + b2s[1], l2 = a2 + b2s[2];
        float m = fmaxf(l0, fmaxf(l1, l2));
        float s = expf(l0 - m) + expf(l1 - m) + expf(l2 - m);
        int tg = targ[p];
        float lt = (tg == 0) ? l0 : ((tg == 1) ? l1 : l2);
        ce = logf(s) + m - lt;
        if (logits_out != nullptr && lane == 0) {
            logits_out[(size_t)p * 3 + 0] = l0;
            logits_out[(size_t)p * 3 + 1] = l1;
            logits_out[(size_t)p * 3 + 2] = l2;
        }
        int argm = 0; float mm = l0;
        if (l1 > mm) { mm = l1; argm = 1; }
        if (l2 > mm) { mm = l2; argm = 2; }
        bool conf = (1.0f / s) > 0.3f;
        int rt = rtype[p];
        if (conf && (argm == 1 || argm == 2)) {
            bool srcIs1 = (argm == 1);
            int src = srcIs1 ? p1 : p2;
            int dst = srcIs1 ? p2 : p1;
            float* sb = (rt == 0) ? sintra : sinter;
            float* cb = (rt == 0) ? cintra : cinter;
            const float* xs = ABX + (size_t)src * NBIG + 1024;  // x[src]
            #pragma unroll
            for (int j = 0; j < NL / 32; j++) {
                int d = j * 32 + lane;
                atomicAdd(&sb[(size_t)dst * NL + d], xs[d]);
            }
            if (lane == 0) atomicAdd(&cb[dst], 1.0f);
        }
    }
    if (lane == 0) ce_s[warp] = (p < P) ? ce : 0.f;
    __syncthreads();
    if (tid == 0) {
        float t = ce_s[0] + ce_s[1] + ce_s[2] + ce_s[3]
                + ce_s[4] + ce_s[5] + ce_s[6] + ce_s[7];
        atomicAdd(lossacc, t);
    }
}

// ---------------- build Z = [x | 0.7*agg_intra | 0.3*agg_inter]; zero other phase
__global__ void zbuild_kernel(const float* __restrict__ x,       // ABX+1024, ld NBIG
                              const float* __restrict__ sintra, const float* __restrict__ sinter,
                              const float* __restrict__ cintra, const float* __restrict__ cinter,
                              float* __restrict__ sintra_o, float* __restrict__ sinter_o,
                              float* __restrict__ cintra_o, float* __restrict__ cinter_o,
                              float* __restrict__ Z, int E)
{
    int i = blockIdx.x * blockDim.x + threadIdx.x;
    if (i >= E * 3 * NL) return;
    int e = i / (3 * NL), j = i % (3 * NL);
    float v;
    if (j < NL) {
        v = x[(size_t)e * NBIG + j];
    } else if (j < 2 * NL) {
        int d = j - NL;
        v = 0.7f * (sintra[(size_t)e * NL + d] + x[(size_t)e * NBIG + d]) / (cintra[e] + 1.0f);
        sintra_o[(size_t)e * NL + d] = 0.f;
    } else {
        int d = j - 2 * NL;
        v = 0.3f * sinter[(size_t)e * NL + d] / fmaxf(cinter[e], 1.0f);
        sinter_o[(size_t)e * NL + d] = 0.f;
        if (d == 0) { cintra_o[e] = 0.f; cinter_o[e] = 0.f; }
    }
    Z[i] = v;
}

__global__ void final_loss_kernel(const float* lp, float* out, int P)
{
    out[0] = (lp[0] + lp[1] * 0.5f + lp[2] * (1.0f / 3.0f)) / (float)P;
}

// ---------------- launch ------------------------------------------------------
extern "C" void kernel_launch(void* const* d_in, const int* in_sizes, int n_in,
                              void* d_out, int out_size)
{
    const float* sent   = (const float*)d_in[0];
    const float* Wproj  = (const float*)d_in[1];
    const float* W1     = (const float*)d_in[2];
    const float* b1     = (const float*)d_in[3];
    const float* W2     = (const float*)d_in[4];
    const float* b2     = (const float*)d_in[5];
    const float* Wself  = (const float*)d_in[6];
    const float* Wintra = (const float*)d_in[7];
    const float* Winter = (const float*)d_in[8];
    const int* esent  = (const int*)d_in[9];
    const int* estart = (const int*)d_in[10];
    const int* elen   = (const int*)d_in[11];
    const int* pair1  = (const int*)d_in[12];
    const int* pair2  = (const int*)d_in[13];
    const int* rtype  = (const int*)d_in[14];
    const int* targ   = (const int*)d_in[15];
    float* out = (float*)d_out;

    int E = in_sizes[9];
    int P = in_sizes[12];
    if (E > E_MAX) E = E_MAX;
    if (P > P_MAX) P = P_MAX;

    float *eemb, *Wbig, *ABX, *Cm, *Z, *Wcat, *lp;
    float *si[2], *se[2], *ci[2], *ce[2];
    cudaGetSymbolAddress((void**)&eemb, g_eemb);
    cudaGetSymbolAddress((void**)&Wbig, g_Wbig);
    cudaGetSymbolAddress((void**)&ABX,  g_ABX);
    cudaGetSymbolAddress((void**)&Cm,   g_Cmat);
    cudaGetSymbolAddress((void**)&Z,    g_Z);
    cudaGetSymbolAddress((void**)&Wcat, g_Wcat);
    cudaGetSymbolAddress((void**)&lp,   g_losspart);
    {
        float* base;
        cudaGetSymbolAddress((void**)&base, g_sintra);
        si[0] = base; si[1] = base + E_MAX * NL;
        cudaGetSymbolAddress((void**)&base, g_sinter);
        se[0] = base; se[1] = base + E_MAX * NL;
        cudaGetSymbolAddress((void**)&base, g_cintra);
        ci[0] = base; ci[1] = base + E_MAX;
        cudaGetSymbolAddress((void**)&base, g_cinter);
        ce[0] = base; ce[1] = base + E_MAX;
    }

    int loff = out_size - 3 * P;
    if (loff < 0) loff = 0;
    float* logits_out = out + loff;

    // 1) extract events  +  prep (pack weights, zero phase-0, zero loss)
    extract_kernel<<<E, D_DIM / 4>>>(sent, esent, estart, elen, eemb);
    {
        long tot = (long)D_DIM * NBIG + 3 * NL * NL + (long)E * NL + E + 4;
        prep_kernel<<<(int)((tot + 255) / 256), 256>>>(W1, Wproj, Wself, Wintra, Winter, E);
    }

    // 2) one big GEMM: ABX = eemb @ Wbig  (2000 x 1152 x 768)
    {
        dim3 g(NBIG / 128, (E + 127) / 128);
        sgemm_t<128, 128, 8, 8, 8, false><<<g, 256>>>(E, NBIG, D_DIM,
                                                      eemb, D_DIM, Wbig, NBIG, ABX, NBIG);
    }

    // 3) three message-passing iterations
    for (int it = 0; it < 3; it++) {
        int ph = it & 1, po = ph ^ 1;
        // C = x @ W1[1536:1664]   (2000 x 512 x 128), x strided inside ABX
        {
            dim3 g(HID / 64, (E + 63) / 64);
            sgemm_t<64, 64, 16, 4, 4, false><<<g, 256>>>(E, HID, NL,
                ABX + 1024, NBIG, W1 + (size_t)1536 * HID, HID, Cm, HID);
        }
        pair_kernel<<<(P + 7) / 8, 256>>>(ABX, Cm, b1, W2, b2,
                                          pair1, pair2, rtype, targ,
                                          si[ph], se[ph], ci[ph], ce[ph],
                                          lp + it, (it == 2) ? logits_out : nullptr, P);
        zbuild_kernel<<<(E * 3 * NL + 255) / 256, 256>>>(ABX + 1024,
                                          si[ph], se[ph], ci[ph], ce[ph],
                                          si[po], se[po], ci[po], ce[po], Z, E);
        // x = relu(Z @ Wcat)  (2000 x 128 x 384), writes back into ABX cols 1024:1152
        {
            dim3 g(NL / 64, (E + 63) / 64);
            sgemm_t<64, 64, 16, 4, 4, true><<<g, 256>>>(E, NL, 3 * NL,
                Z, 3 * NL, Wcat, NL, ABX + 1024, NBIG);
        }
    }

    // 4) loss
    final_loss_kernel<<<1, 1>>>(lp, out, P);
}

// round 3
// speedup vs baseline: 2.9611x; 1.2158x over previous
#include <cuda_runtime.h>
#include <math.h>

#define NSENT 64
#define S_LEN 512
#define D_DIM 768
#define NL    128
#define HID   512
#define CLS   3
#define E_MAX 2000
#define P_MAX 20000
#define NBIG  1152            // 512(A0) + 512(B0) + 128(x0)

// ---------------- static device scratch ----------------
__device__ float g_eemb [E_MAX * D_DIM];
__device__ float g_Wbig [D_DIM * NBIG];        // [W1a | W1b | Wproj]
__device__ float g_ABX  [E_MAX * NBIG];        // [A0 | B0 | x0]
__device__ float g_Ap   [E_MAX * HID];         // A0 + C + b1
__device__ float g_Bp   [E_MAX * HID];         // B0 - C
__device__ float g_xbuf [2][E_MAX * NL];
__device__ float g_sintra[2][E_MAX * NL];
__device__ float g_sinter[2][E_MAX * NL];
__device__ float g_cintra[2][E_MAX];
__device__ float g_cinter[2][E_MAX];
__device__ float g_Wcat [3 * NL * NL];
__device__ float g_losspart[4];

// ---------------- event extraction (float4) ----------------
__global__ void extract_kernel(const float* __restrict__ sent,
                               const int* __restrict__ esent,
                               const int* __restrict__ estart,
                               const int* __restrict__ elen,
                               float* __restrict__ eemb)
{
    int e = blockIdx.x;
    int len = elen[e] + 1;
    int st  = estart[e];
    int snt = esent[e];
    float inv = 1.0f / (float)len;
    const float4* base = (const float4*)(sent + (size_t)snt * S_LEN * D_DIM);
    int d4 = threadIdx.x;              // blockDim = 192
    float4 acc = make_float4(0.f, 0.f, 0.f, 0.f);
    for (int o = 0; o < len; o++) {
        int idx = st + o; if (idx > S_LEN - 1) idx = S_LEN - 1;
        float4 v = base[(size_t)idx * (D_DIM / 4) + d4];
        acc.x += v.x; acc.y += v.y; acc.z += v.z; acc.w += v.w;
    }
    acc.x *= inv; acc.y *= inv; acc.z *= inv; acc.w *= inv;
    ((float4*)(eemb + (size_t)e * D_DIM))[d4] = acc;
}

// ---------------- prep: pack Wbig, Wcat, zero phase-0 + loss ------------------
__global__ void prep_kernel(const float* __restrict__ W1,
                            const float* __restrict__ Wproj,
                            const float* __restrict__ Wself,
                            const float* __restrict__ Wintra,
                            const float* __restrict__ Winter,
                            int E)
{
    long i = (long)blockIdx.x * blockDim.x + threadIdx.x;
    const long N_WBIG = (long)D_DIM * NBIG;
    const long N_WCAT = 3 * NL * NL;
    if (i < N_WBIG) {
        int k = (int)(i / NBIG), n = (int)(i % NBIG);
        float v;
        if (n < 512)        v = W1[(size_t)k * HID + n];
        else if (n < 1024)  v = W1[(size_t)(768 + k) * HID + (n - 512)];
        else                v = Wproj[(size_t)k * NL + (n - 1024)];
        g_Wbig[i] = v;
        return;
    }
    i -= N_WBIG;
    if (i < N_WCAT) {
        int k = (int)(i / NL), d = (int)(i % NL);
        const float* src = (k < NL) ? Wself : ((k < 2 * NL) ? Wintra : Winter);
        g_Wcat[i] = src[(k % NL) * NL + d];
        return;
    }
    i -= N_WCAT;
    if (i < (long)E * NL) { g_sintra[0][i] = 0.f; g_sinter[0][i] = 0.f; return; }
    i -= (long)E * NL;
    if (i < E) { g_cintra[0][i] = 0.f; g_cinter[0][i] = 0.f; return; }
    i -= E;
    if (i < 4) g_losspart[i] = 0.f;
}

// ---------------- big 128x128x16 double-buffered SGEMM (fixed shapes) ---------
// C[M,N] = A[M,K] * B[K,N]; N % 128 == 0, K % 16 == 0; only M guarded.
__global__ void __launch_bounds__(256, 1) sgemm_big(
    int M, int N, int K,
    const float* __restrict__ A, int lda,
    const float* __restrict__ B, int ldb,
    float* __restrict__ C, int ldc)
{
    __shared__ float As[2][16][132];
    __shared__ float Bs[2][16][128];
    const int tid  = threadIdx.x;
    const int brow = blockIdx.y * 128;
    const int bcol = blockIdx.x * 128;

    const int ar0 = tid >> 2;              // 0..63
    const int ac  = (tid & 3) * 4;         // 0,4,8,12
    const int bkr = tid >> 5;              // 0..7
    const int bc  = (tid & 31) * 4;        // 0..124

    const int tx = tid & 15;
    const int ty = tid >> 4;

    float4 a0, a1, b0, b1;
    // preload tile 0
    a0 = make_float4(0.f,0.f,0.f,0.f); a1 = a0;
    if (brow + ar0      < M) a0 = *(const float4*)(A + (size_t)(brow + ar0)      * lda + ac);
    if (brow + ar0 + 64 < M) a1 = *(const float4*)(A + (size_t)(brow + ar0 + 64) * lda + ac);
    b0 = *(const float4*)(B + (size_t)bkr       * ldb + bcol + bc);
    b1 = *(const float4*)(B + (size_t)(bkr + 8) * ldb + bcol + bc);
    As[0][ac+0][ar0] = a0.x; As[0][ac+1][ar0] = a0.y; As[0][ac+2][ar0] = a0.z; As[0][ac+3][ar0] = a0.w;
    As[0][ac+0][ar0+64] = a1.x; As[0][ac+1][ar0+64] = a1.y; As[0][ac+2][ar0+64] = a1.z; As[0][ac+3][ar0+64] = a1.w;
    *(float4*)&Bs[0][bkr][bc]     = b0;
    *(float4*)&Bs[0][bkr + 8][bc] = b1;
    __syncthreads();

    float acc[8][8];
    #pragma unroll
    for (int i = 0; i < 8; i++)
        #pragma unroll
        for (int j = 0; j < 8; j++) acc[i][j] = 0.f;

    int buf = 0;
    for (int k0 = 16; k0 < K; k0 += 16) {
        a0 = make_float4(0.f,0.f,0.f,0.f); a1 = a0;
        if (brow + ar0      < M) a0 = *(const float4*)(A + (size_t)(brow + ar0)      * lda + k0 + ac);
        if (brow + ar0 + 64 < M) a1 = *(const float4*)(A + (size_t)(brow + ar0 + 64) * lda + k0 + ac);
        b0 = *(const float4*)(B + (size_t)(k0 + bkr)     * ldb + bcol + bc);
        b1 = *(const float4*)(B + (size_t)(k0 + bkr + 8) * ldb + bcol + bc);

        #pragma unroll
        for (int k = 0; k < 16; k++) {
            float av[8], bv[8];
            *(float4*)&av[0] = *(const float4*)&As[buf][k][ty * 8];
            *(float4*)&av[4] = *(const float4*)&As[buf][k][ty * 8 + 4];
            *(float4*)&bv[0] = *(const float4*)&Bs[buf][k][tx * 8];
            *(float4*)&bv[4] = *(const float4*)&Bs[buf][k][tx * 8 + 4];
            #pragma unroll
            for (int i = 0; i < 8; i++)
                #pragma unroll
                for (int j = 0; j < 8; j++)
                    acc[i][j] = fmaf(av[i], bv[j], acc[i][j]);
        }

        int nb = buf ^ 1;
        As[nb][ac+0][ar0] = a0.x; As[nb][ac+1][ar0] = a0.y; As[nb][ac+2][ar0] = a0.z; As[nb][ac+3][ar0] = a0.w;
        As[nb][ac+0][ar0+64] = a1.x; As[nb][ac+1][ar0+64] = a1.y; As[nb][ac+2][ar0+64] = a1.z; As[nb][ac+3][ar0+64] = a1.w;
        *(float4*)&Bs[nb][bkr][bc]     = b0;
        *(float4*)&Bs[nb][bkr + 8][bc] = b1;
        __syncthreads();
        buf = nb;
    }
    #pragma unroll
    for (int k = 0; k < 16; k++) {
        float av[8], bv[8];
        *(float4*)&av[0] = *(const float4*)&As[buf][k][ty * 8];
        *(float4*)&av[4] = *(const float4*)&As[buf][k][ty * 8 + 4];
        *(float4*)&bv[0] = *(const float4*)&Bs[buf][k][tx * 8];
        *(float4*)&bv[4] = *(const float4*)&Bs[buf][k][tx * 8 + 4];
        #pragma unroll
        for (int i = 0; i < 8; i++)
            #pragma unroll
            for (int j = 0; j < 8; j++)
                acc[i][j] = fmaf(av[i], bv[j], acc[i][j]);
    }

    #pragma unroll
    for (int i = 0; i < 8; i++) {
        int r = brow + ty * 8 + i;
        if (r >= M) continue;
        #pragma unroll
        for (int v = 0; v < 2; v++) {
            float4 o;
            o.x = acc[i][v*4+0]; o.y = acc[i][v*4+1]; o.z = acc[i][v*4+2]; o.w = acc[i][v*4+3];
            *(float4*)(C + (size_t)r * ldc + bcol + tx * 8 + v * 4) = o;
        }
    }
}

// ---------------- fused C-GEMM: C = x@W1c, writes Ap=A0+C+b1, Bp=B0-C ---------
// 64x64x16, 4x4 microtile. M=E, N=512, K=128.
__global__ void __launch_bounds__(256) cgemm_fused(
    int M,
    const float* __restrict__ xin, int xld,
    const float* __restrict__ W1c,                 // 128x512 (= W1+1536*HID)
    const float* __restrict__ ABX,                 // A0 at +0, B0 at +512, ld NBIG
    const float* __restrict__ b1,
    float* __restrict__ Ap, float* __restrict__ Bp)
{
    const int BM = 64, BN = 64, BK = 16;
    __shared__ float As[2][BK][BM];
    __shared__ float Bs[2][BK][BN];
    const int tid  = threadIdx.x;
    const int brow = blockIdx.y * BM;
    const int bcol = blockIdx.x * BN;
    const int ar = tid >> 2, ac = (tid & 3) * 4;
    const int br = tid >> 4, bc = (tid & 15) * 4;
    const int tx = tid & 15, ty = tid >> 4;

    float4 areg = make_float4(0.f,0.f,0.f,0.f), breg;
    if (brow + ar < M) areg = *(const float4*)(xin + (size_t)(brow + ar) * xld + ac);
    breg = *(const float4*)(W1c + (size_t)br * HID + bcol + bc);
    As[0][ac+0][ar] = areg.x; As[0][ac+1][ar] = areg.y; As[0][ac+2][ar] = areg.z; As[0][ac+3][ar] = areg.w;
    *(float4*)&Bs[0][br][bc] = breg;
    __syncthreads();

    float acc[4][4];
    #pragma unroll
    for (int i = 0; i < 4; i++)
        #pragma unroll
        for (int j = 0; j < 4; j++) acc[i][j] = 0.f;

    int buf = 0;
    for (int k0 = BK; k0 < NL; k0 += BK) {
        areg = make_float4(0.f,0.f,0.f,0.f);
        if (brow + ar < M) areg = *(const float4*)(xin + (size_t)(brow + ar) * xld + k0 + ac);
        breg = *(const float4*)(W1c + (size_t)(k0 + br) * HID + bcol + bc);
        #pragma unroll
        for (int k = 0; k < BK; k++) {
            float av[4], bv[4];
            *(float4*)av = *(const float4*)&As[buf][k][ty * 4];
            *(float4*)bv = *(const float4*)&Bs[buf][k][tx * 4];
            #pragma unroll
            for (int i = 0; i < 4; i++)
                #pragma unroll
                for (int j = 0; j < 4; j++)
                    acc[i][j] = fmaf(av[i], bv[j], acc[i][j]);
        }
        int nb = buf ^ 1;
        As[nb][ac+0][ar] = areg.x; As[nb][ac+1][ar] = areg.y; As[nb][ac+2][ar] = areg.z; As[nb][ac+3][ar] = areg.w;
        *(float4*)&Bs[nb][br][bc] = breg;
        __syncthreads();
        buf = nb;
    }
    #pragma unroll
    for (int k = 0; k < BK; k++) {
        float av[4], bv[4];
        *(float4*)av = *(const float4*)&As[buf][k][ty * 4];
        *(float4*)bv = *(const float4*)&Bs[buf][k][tx * 4];
        #pragma unroll
        for (int i = 0; i < 4; i++)
            #pragma unroll
            for (int j = 0; j < 4; j++)
                acc[i][j] = fmaf(av[i], bv[j], acc[i][j]);
    }

    int cc = bcol + tx * 4;
    float4 b1v = *(const float4*)(b1 + cc);
    #pragma unroll
    for (int i = 0; i < 4; i++) {
        int r = brow + ty * 4 + i;
        if (r >= M) continue;
        float4 a0v = *(const float4*)(ABX + (size_t)r * NBIG + cc);
        float4 b0v = *(const float4*)(ABX + (size_t)r * NBIG + 512 + cc);
        float4 oa, ob;
        oa.x = a0v.x + acc[i][0] + b1v.x; ob.x = b0v.x - acc[i][0];
        oa.y = a0v.y + acc[i][1] + b1v.y; ob.y = b0v.y - acc[i][1];
        oa.z = a0v.z + acc[i][2] + b1v.z; ob.z = b0v.z - acc[i][2];
        oa.w = a0v.w + acc[i][3] + b1v.w; ob.w = b0v.w - acc[i][3];
        *(float4*)(Ap + (size_t)r * HID + cc) = oa;
        *(float4*)(Bp + (size_t)r * HID + cc) = ob;
    }
}

// ---------------- fused update GEMM: x_out = relu(Z@Wcat), Z built on the fly -
// 64x64x16, 4x4 microtile. M=E, N=128, K=384.
__device__ __forceinline__ float4 z_load(
    const float* __restrict__ xin, int xld,
    const float* __restrict__ sintra, const float* __restrict__ sinter,
    const float* __restrict__ cintra, const float* __restrict__ cinter,
    int r, int kg)
{
    int seg = kg >> 7, d = kg & 127;
    if (seg == 0) {
        return *(const float4*)(xin + (size_t)r * xld + d);
    } else if (seg == 1) {
        float4 s = *(const float4*)(sintra + (size_t)r * NL + d);
        float4 xv = *(const float4*)(xin + (size_t)r * xld + d);
        float rc = 0.7f / (cintra[r] + 1.0f);
        return make_float4((s.x + xv.x) * rc, (s.y + xv.y) * rc,
                           (s.z + xv.z) * rc, (s.w + xv.w) * rc);
    } else {
        float4 s = *(const float4*)(sinter + (size_t)r * NL + d);
        float rc = 0.3f / fmaxf(cinter[r], 1.0f);
        return make_float4(s.x * rc, s.y * rc, s.z * rc, s.w * rc);
    }
}

__global__ void __launch_bounds__(256) upd_fused(
    int M,
    const float* __restrict__ xin, int xld,
    const float* __restrict__ sintra, const float* __restrict__ sinter,
    const float* __restrict__ cintra, const float* __restrict__ cinter,
    const float* __restrict__ Wcat,                // 384x128
    float* __restrict__ xout)                      // ld NL
{
    const int BM = 64, BN = 64, BK = 16, KTOT = 3 * NL;
    __shared__ float As[2][BK][BM];
    __shared__ float Bs[2][BK][BN];
    const int tid  = threadIdx.x;
    const int brow = blockIdx.y * BM;
    const int bcol = blockIdx.x * BN;
    const int ar = tid >> 2, ac = (tid & 3) * 4;
    const int br = tid >> 4, bc = (tid & 15) * 4;
    const int tx = tid & 15, ty = tid >> 4;

    float4 areg = make_float4(0.f,0.f,0.f,0.f), breg;
    if (brow + ar < M) areg = z_load(xin, xld, sintra, sinter, cintra, cinter, brow + ar, ac);
    breg = *(const float4*)(Wcat + (size_t)br * NL + bcol + bc);
    As[0][ac+0][ar] = areg.x; As[0][ac+1][ar] = areg.y; As[0][ac+2][ar] = areg.z; As[0][ac+3][ar] = areg.w;
    *(float4*)&Bs[0][br][bc] = breg;
    __syncthreads();

    float acc[4][4];
    #pragma unroll
    for (int i = 0; i < 4; i++)
        #pragma unroll
        for (int j = 0; j < 4; j++) acc[i][j] = 0.f;

    int buf = 0;
    for (int k0 = BK; k0 < KTOT; k0 += BK) {
        areg = make_float4(0.f,0.f,0.f,0.f);
        if (brow + ar < M) areg = z_load(xin, xld, sintra, sinter, cintra, cinter, brow + ar, k0 + ac);
        breg = *(const float4*)(Wcat + (size_t)(k0 + br) * NL + bcol + bc);
        #pragma unroll
        for (int k = 0; k < BK; k++) {
            float av[4], bv[4];
            *(float4*)av = *(const float4*)&As[buf][k][ty * 4];
            *(float4*)bv = *(const float4*)&Bs[buf][k][tx * 4];
            #pragma unroll
            for (int i = 0; i < 4; i++)
                #pragma unroll
                for (int j = 0; j < 4; j++)
                    acc[i][j] = fmaf(av[i], bv[j], acc[i][j]);
        }
        int nb = buf ^ 1;
        As[nb][ac+0][ar] = areg.x; As[nb][ac+1][ar] = areg.y; As[nb][ac+2][ar] = areg.z; As[nb][ac+3][ar] = areg.w;
        *(float4*)&Bs[nb][br][bc] = breg;
        __syncthreads();
        buf = nb;
    }
    #pragma unroll
    for (int k = 0; k < BK; k++) {
        float av[4], bv[4];
        *(float4*)av = *(const float4*)&As[buf][k][ty * 4];
        *(float4*)bv = *(const float4*)&Bs[buf][k][tx * 4];
        #pragma unroll
        for (int i = 0; i < 4; i++)
            #pragma unroll
            for (int j = 0; j < 4; j++)
                acc[i][j] = fmaf(av[i], bv[j], acc[i][j]);
    }

    #pragma unroll
    for (int i = 0; i < 4; i++) {
        int r = brow + ty * 4 + i;
        if (r >= M) continue;
        float4 o;
        o.x = fmaxf(acc[i][0], 0.f); o.y = fmaxf(acc[i][1], 0.f);
        o.z = fmaxf(acc[i][2], 0.f); o.w = fmaxf(acc[i][3], 0.f);
        *(float4*)(xout + (size_t)r * NL + bcol + tx * 4) = o;
    }
}

// ---------------- per-pair: logits, CE, masks, scatter; zero other phase ------
__global__ void __launch_bounds__(256) pair_kernel(
    const float* __restrict__ Ap, const float* __restrict__ Bp,
    const float* __restrict__ xin, int xld,
    const float* __restrict__ W2, const float* __restrict__ b2,
    const int* __restrict__ pair1, const int* __restrict__ pair2,
    const int* __restrict__ rtype, const int* __restrict__ targ,
    float* sintra, float* sinter, float* cintra, float* cinter,
    float* si_o, float* se_o, float* ci_o, float* ce_o,
    float* lossacc, float* logits_out, int P, int E)
{
    __shared__ float W2s0[HID], W2s1[HID], W2s2[HID];
    __shared__ float b2s[CLS];
    __shared__ float ce_s[8];
    int tid = threadIdx.x;
    for (int i = tid; i < HID; i += 256) {
        W2s0[i] = W2[i * 3 + 0];
        W2s1[i] = W2[i * 3 + 1];
        W2s2[i] = W2[i * 3 + 2];
    }
    if (tid < CLS) b2s[tid] = b2[tid];

    // fused zeroing of the OTHER phase's segment buffers (disjoint memory)
    {
        long idx = (long)blockIdx.x * 256 + tid;
        long stride = (long)gridDim.x * 256;
        for (long i = idx; i < (long)E * NL; i += stride) { si_o[i] = 0.f; se_o[i] = 0.f; }
        for (long i = idx; i < E; i += stride) { ci_o[i] = 0.f; ce_o[i] = 0.f; }
    }
    __syncthreads();

    int warp = tid >> 5, lane = tid & 31;
    int p = blockIdx.x * 8 + warp;
    float ce = 0.f;
    if (p < P) {
        int p1 = pair1[p], p2 = pair2[p];
        const float4* a4 = (const float4*)(Ap + (size_t)p1 * HID);
        const float4* b4 = (const float4*)(Bp + (size_t)p2 * HID);
        float a0 = 0.f, a1 = 0.f, a2 = 0.f;
        #pragma unroll
        for (int j = 0; j < 4; j++) {
            int i4 = j * 32 + lane;            // float4 index 0..127
            float4 av = a4[i4], bv = b4[i4];
            float4 h;
            h.x = fmaxf(av.x + bv.x, 0.f);
            h.y = fmaxf(av.y + bv.y, 0.f);
            h.z = fmaxf(av.z + bv.z, 0.f);
            h.w = fmaxf(av.w + bv.w, 0.f);
            int base = i4 * 4;
            float4 w0 = *(const float4*)&W2s0[base];
            float4 w1 = *(const float4*)&W2s1[base];
            float4 w2 = *(const float4*)&W2s2[base];
            a0 = fmaf(h.x, w0.x, fmaf(h.y, w0.y, fmaf(h.z, w0.z, fmaf(h.w, w0.w, a0))));
            a1 = fmaf(h.x, w1.x, fmaf(h.y, w1.y, fmaf(h.z, w1.z, fmaf(h.w, w1.w, a1))));
            a2 = fmaf(h.x, w2.x, fmaf(h.y, w2.y, fmaf(h.z, w2.z, fmaf(h.w, w2.w, a2))));
        }
        #pragma unroll
        for (int o = 16; o; o >>= 1) {
            a0 += __shfl_xor_sync(0xffffffffu, a0, o);
            a1 += __shfl_xor_sync(0xffffffffu, a1, o);
            a2 += __shfl_xor_sync(0xffffffffu, a2, o);
        }
        float l0 = a0 + b2s[0], l1 = a1 + b2s[1], l2 = a2 + b2s[2];
        float m = fmaxf(l0, fmaxf(l1, l2));
        float s = expf(l0 - m) + expf(l1 - m) + expf(l2 - m);
        int tg = targ[p];
        float lt = (tg == 0) ? l0 : ((tg == 1) ? l1 : l2);
        ce = logf(s) + m - lt;
        if (logits_out != nullptr && lane == 0) {
            logits_out[(size_t)p * 3 + 0] = l0;
            logits_out[(size_t)p * 3 + 1] = l1;
            logits_out[(size_t)p * 3 + 2] = l2;
        }
        int argm = 0; float mm = l0;
        if (l1 > mm) { mm = l1; argm = 1; }
        if (l2 > mm) { mm = l2; argm = 2; }
        bool conf = (1.0f / s) > 0.3f;
        int rt = rtype[p];
        if (conf && (argm == 1 || argm == 2)) {
            bool srcIs1 = (argm == 1);
            int src = srcIs1 ? p1 : p2;
            int dst = srcIs1 ? p2 : p1;
            float* sb = (rt == 0) ? sintra : sinter;
            float* cb = (rt == 0) ? cintra : cinter;
            const float* xs = xin + (size_t)src * xld;
            #pragma unroll
            for (int j = 0; j < NL / 32; j++) {
                int d = j * 32 + lane;
                atomicAdd(&sb[(size_t)dst * NL + d], xs[d]);
            }
            if (lane == 0) atomicAdd(&cb[dst], 1.0f);
        }
    }
    if (lane == 0) ce_s[warp] = (p < P) ? ce : 0.f;
    __syncthreads();
    if (tid == 0) {
        float t = ce_s[0] + ce_s[1] + ce_s[2] + ce_s[3]
                + ce_s[4] + ce_s[5] + ce_s[6] + ce_s[7];
        atomicAdd(lossacc, t);
    }
}

__global__ void final_loss_kernel(const float* lp, float* out, int P)
{
    out[0] = (lp[0] + lp[1] * 0.5f + lp[2] * (1.0f / 3.0f)) / (float)P;
}

// ---------------- launch ------------------------------------------------------
extern "C" void kernel_launch(void* const* d_in, const int* in_sizes, int n_in,
                              void* d_out, int out_size)
{
    const float* sent   = (const float*)d_in[0];
    const float* Wproj  = (const float*)d_in[1];
    const float* W1     = (const float*)d_in[2];
    const float* b1     = (const float*)d_in[3];
    const float* W2     = (const float*)d_in[4];
    const float* b2     = (const float*)d_in[5];
    const float* Wself  = (const float*)d_in[6];
    const float* Wintra = (const float*)d_in[7];
    const float* Winter = (const float*)d_in[8];
    const int* esent  = (const int*)d_in[9];
    const int* estart = (const int*)d_in[10];
    const int* elen   = (const int*)d_in[11];
    const int* pair1  = (const int*)d_in[12];
    const int* pair2  = (const int*)d_in[13];
    const int* rtype  = (const int*)d_in[14];
    const int* targ   = (const int*)d_in[15];
    float* out = (float*)d_out;

    int E = in_sizes[9];
    int P = in_sizes[12];
    if (E > E_MAX) E = E_MAX;
    if (P > P_MAX) P = P_MAX;

    float *eemb, *Wbig, *ABX, *Ap, *Bp, *Wcat, *lp;
    float *xb[2], *si[2], *se[2], *ci[2], *ce[2];
    cudaGetSymbolAddress((void**)&eemb, g_eemb);
    cudaGetSymbolAddress((void**)&Wbig, g_Wbig);
    cudaGetSymbolAddress((void**)&ABX,  g_ABX);
    cudaGetSymbolAddress((void**)&Ap,   g_Ap);
    cudaGetSymbolAddress((void**)&Bp,   g_Bp);
    cudaGetSymbolAddress((void**)&Wcat, g_Wcat);
    cudaGetSymbolAddress((void**)&lp,   g_losspart);
    {
        float* base;
        cudaGetSymbolAddress((void**)&base, g_xbuf);
        xb[0] = base; xb[1] = base + E_MAX * NL;
        cudaGetSymbolAddress((void**)&base, g_sintra);
        si[0] = base; si[1] = base + E_MAX * NL;
        cudaGetSymbolAddress((void**)&base, g_sinter);
        se[0] = base; se[1] = base + E_MAX * NL;
        cudaGetSymbolAddress((void**)&base, g_cintra);
        ci[0] = base; ci[1] = base + E_MAX;
        cudaGetSymbolAddress((void**)&base, g_cinter);
        ce[0] = base; ce[1] = base + E_MAX;
    }

    int loff = out_size - 3 * P;
    if (loff < 0) loff = 0;
    float* logits_out = out + loff;

    // 1) extract + prep
    extract_kernel<<<E, D_DIM / 4>>>(sent, esent, estart, elen, eemb);
    {
        long tot = (long)D_DIM * NBIG + 3 * NL * NL + (long)E * NL + E + 4;
        prep_kernel<<<(int)((tot + 255) / 256), 256>>>(W1, Wproj, Wself, Wintra, Winter, E);
    }

    // 2) one big GEMM: ABX = eemb @ Wbig (2000 x 1152 x 768)
    {
        dim3 g(NBIG / 128, (E + 127) / 128);
        sgemm_big<<<g, 256>>>(E, NBIG, D_DIM, eemb, D_DIM, Wbig, NBIG, ABX, NBIG);
    }

    // 3) three iterations
    const float* W1c = W1 + (size_t)1536 * HID;
    for (int it = 0; it < 3; it++) {
        int ph = it & 1, po = ph ^ 1;
        const float* xin = (it == 0) ? (ABX + 1024) : xb[(it - 1) & 1];
        int xld = (it == 0) ? NBIG : NL;
        float* xout = xb[it & 1];

        {   // Ap/Bp fold GEMM (2000 x 512 x 128)
            dim3 g(HID / 64, (E + 63) / 64);
            cgemm_fused<<<g, 256>>>(E, xin, xld, W1c, ABX, b1, Ap, Bp);
        }
        pair_kernel<<<(P + 7) / 8, 256>>>(Ap, Bp, xin, xld, W2, b2,
                                          pair1, pair2, rtype, targ,
                                          si[ph], se[ph], ci[ph], ce[ph],
                                          si[po], se[po], ci[po], ce[po],
                                          lp + it, (it == 2) ? logits_out : nullptr, P, E);
        {   // x_out = relu(Z @ Wcat)  (2000 x 128 x 384), Z built on the fly
            dim3 g(NL / 64, (E + 63) / 64);
            upd_fused<<<g, 256>>>(E, xin, xld,
                                  si[ph], se[ph], ci[ph], ce[ph],
                                  Wcat, xout);
        }
    }

    // 4) loss
    final_loss_kernel<<<1, 1>>>(lp, out, P);
}

// round 4
// speedup vs baseline: 2.9863x; 1.0085x over previous
#include <cuda_runtime.h>
#include <math.h>

#define NSENT 64
#define S_LEN 512
#define D_DIM 768
#define NL    128
#define HID   512
#define CLS   3
#define E_MAX 2000
#define P_MAX 20000
#define NBIG  1152            // 512(A0) + 512(B0) + 128(x0)

typedef unsigned long long u64;

// ---------------- f32x2 packed helpers (Blackwell FFMA2) ----------------
__device__ __forceinline__ u64 pack2(float x, float y) {
    u64 r;
    asm("mov.b64 %0, {%1, %2};" : "=l"(r) : "f"(x), "f"(y));
    return r;
}
__device__ __forceinline__ void unpack2(u64 v, float& x, float& y) {
    asm("mov.b64 {%0, %1}, %2;" : "=f"(x), "=f"(y) : "l"(v));
}
__device__ __forceinline__ u64 fma2(u64 a, u64 b, u64 c) {
    u64 d;
    asm("fma.rn.f32x2 %0, %1, %2, %3;" : "=l"(d) : "l"(a), "l"(b), "l"(c));
    return d;
}

// ---------------- static device scratch ----------------
__device__ float g_eemb [E_MAX * D_DIM];
__device__ float g_Wbig [D_DIM * NBIG];        // [W1a | W1b | Wproj]
__device__ float g_ABX  [E_MAX * NBIG];        // [A0 | B0 | x0]
__device__ float g_Ap   [E_MAX * HID];         // A0 + C + b1
__device__ float g_Bp   [E_MAX * HID];         // B0 - C
__device__ float g_xbuf [2][E_MAX * NL];
__device__ float g_sintra[2][E_MAX * NL];
__device__ float g_sinter[2][E_MAX * NL];
__device__ float g_cintra[2][E_MAX];
__device__ float g_cinter[2][E_MAX];
__device__ float g_Wcat [3 * NL * NL];
__device__ float g_losspart[4];

// ---------------- event extraction (float4) ----------------
__global__ void extract_kernel(const float* __restrict__ sent,
                               const int* __restrict__ esent,
                               const int* __restrict__ estart,
                               const int* __restrict__ elen,
                               float* __restrict__ eemb)
{
    int e = blockIdx.x;
    int len = elen[e] + 1;
    int st  = estart[e];
    int snt = esent[e];
    float inv = 1.0f / (float)len;
    const float4* base = (const float4*)(sent + (size_t)snt * S_LEN * D_DIM);
    int d4 = threadIdx.x;              // blockDim = 192
    float4 acc = make_float4(0.f, 0.f, 0.f, 0.f);
    for (int o = 0; o < len; o++) {
        int idx = st + o; if (idx > S_LEN - 1) idx = S_LEN - 1;
        float4 v = base[(size_t)idx * (D_DIM / 4) + d4];
        acc.x += v.x; acc.y += v.y; acc.z += v.z; acc.w += v.w;
    }
    acc.x *= inv; acc.y *= inv; acc.z *= inv; acc.w *= inv;
    ((float4*)(eemb + (size_t)e * D_DIM))[d4] = acc;
}

// ---------------- prep: pack Wbig, Wcat, zero phase-0 + loss ------------------
__global__ void prep_kernel(const float* __restrict__ W1,
                            const float* __restrict__ Wproj,
                            const float* __restrict__ Wself,
                            const float* __restrict__ Wintra,
                            const float* __restrict__ Winter,
                            int E)
{
    long i = (long)blockIdx.x * blockDim.x + threadIdx.x;
    const long N_WBIG = (long)D_DIM * NBIG;
    const long N_WCAT = 3 * NL * NL;
    if (i < N_WBIG) {
        int k = (int)(i / NBIG), n = (int)(i % NBIG);
        float v;
        if (n < 512)        v = W1[(size_t)k * HID + n];
        else if (n < 1024)  v = W1[(size_t)(768 + k) * HID + (n - 512)];
        else                v = Wproj[(size_t)k * NL + (n - 1024)];
        g_Wbig[i] = v;
        return;
    }
    i -= N_WBIG;
    if (i < N_WCAT) {
        int k = (int)(i / NL), d = (int)(i % NL);
        const float* src = (k < NL) ? Wself : ((k < 2 * NL) ? Wintra : Winter);
        g_Wcat[i] = src[(k % NL) * NL + d];
        return;
    }
    i -= N_WCAT;
    if (i < (long)E * NL) { g_sintra[0][i] = 0.f; g_sinter[0][i] = 0.f; return; }
    i -= (long)E * NL;
    if (i < E) { g_cintra[0][i] = 0.f; g_cinter[0][i] = 0.f; return; }
    i -= E;
    if (i < 4) g_losspart[i] = 0.f;
}

// ---------------- big 128x128x16 double-buffered SGEMM, FFMA2 inner ----------
// C[M,N] = A[M,K] * B[K,N]; N % 128 == 0, K % 16 == 0; only M guarded.
__global__ void __launch_bounds__(256, 1) sgemm_big(
    int M, int N, int K,
    const float* __restrict__ A, int lda,
    const float* __restrict__ B, int ldb,
    float* __restrict__ C, int ldc)
{
    __shared__ float As[2][16][132];
    __shared__ float Bs[2][16][128];
    const int tid  = threadIdx.x;
    const int brow = blockIdx.y * 128;
    const int bcol = blockIdx.x * 128;

    const int ar0 = tid >> 2;              // 0..63
    const int ac  = (tid & 3) * 4;         // 0,4,8,12
    const int bkr = tid >> 5;              // 0..7
    const int bc  = (tid & 31) * 4;        // 0..124

    const int tx = tid & 15;
    const int ty = tid >> 4;

    float4 a0, a1, b0, b1;
    a0 = make_float4(0.f,0.f,0.f,0.f); a1 = a0;
    if (brow + ar0      < M) a0 = *(const float4*)(A + (size_t)(brow + ar0)      * lda + ac);
    if (brow + ar0 + 64 < M) a1 = *(const float4*)(A + (size_t)(brow + ar0 + 64) * lda + ac);
    b0 = *(const float4*)(B + (size_t)bkr       * ldb + bcol + bc);
    b1 = *(const float4*)(B + (size_t)(bkr + 8) * ldb + bcol + bc);
    As[0][ac+0][ar0] = a0.x; As[0][ac+1][ar0] = a0.y; As[0][ac+2][ar0] = a0.z; As[0][ac+3][ar0] = a0.w;
    As[0][ac+0][ar0+64] = a1.x; As[0][ac+1][ar0+64] = a1.y; As[0][ac+2][ar0+64] = a1.z; As[0][ac+3][ar0+64] = a1.w;
    *(float4*)&Bs[0][bkr][bc]     = b0;
    *(float4*)&Bs[0][bkr + 8][bc] = b1;
    __syncthreads();

    u64 acc[8][4];
    #pragma unroll
    for (int i = 0; i < 8; i++)
        #pragma unroll
        for (int j = 0; j < 4; j++) acc[i][j] = 0ull;

    int buf = 0;
    for (int k0 = 16; k0 < K; k0 += 16) {
        a0 = make_float4(0.f,0.f,0.f,0.f); a1 = a0;
        if (brow + ar0      < M) a0 = *(const float4*)(A + (size_t)(brow + ar0)      * lda + k0 + ac);
        if (brow + ar0 + 64 < M) a1 = *(const float4*)(A + (size_t)(brow + ar0 + 64) * lda + k0 + ac);
        b0 = *(const float4*)(B + (size_t)(k0 + bkr)     * ldb + bcol + bc);
        b1 = *(const float4*)(B + (size_t)(k0 + bkr + 8) * ldb + bcol + bc);

        #pragma unroll
        for (int k = 0; k < 16; k++) {
            float av[8];
            *(float4*)&av[0] = *(const float4*)&As[buf][k][ty * 8];
            *(float4*)&av[4] = *(const float4*)&As[buf][k][ty * 8 + 4];
            float4 bq0 = *(const float4*)&Bs[buf][k][tx * 8];
            float4 bq1 = *(const float4*)&Bs[buf][k][tx * 8 + 4];
            u64 bp[4];
            bp[0] = pack2(bq0.x, bq0.y); bp[1] = pack2(bq0.z, bq0.w);
            bp[2] = pack2(bq1.x, bq1.y); bp[3] = pack2(bq1.z, bq1.w);
            #pragma unroll
            for (int i = 0; i < 8; i++) {
                u64 ad = pack2(av[i], av[i]);
                #pragma unroll
                for (int j = 0; j < 4; j++)
                    acc[i][j] = fma2(ad, bp[j], acc[i][j]);
            }
        }

        int nb = buf ^ 1;
        As[nb][ac+0][ar0] = a0.x; As[nb][ac+1][ar0] = a0.y; As[nb][ac+2][ar0] = a0.z; As[nb][ac+3][ar0] = a0.w;
        As[nb][ac+0][ar0+64] = a1.x; As[nb][ac+1][ar0+64] = a1.y; As[nb][ac+2][ar0+64] = a1.z; As[nb][ac+3][ar0+64] = a1.w;
        *(float4*)&Bs[nb][bkr][bc]     = b0;
        *(float4*)&Bs[nb][bkr + 8][bc] = b1;
        __syncthreads();
        buf = nb;
    }
    #pragma unroll
    for (int k = 0; k < 16; k++) {
        float av[8];
        *(float4*)&av[0] = *(const float4*)&As[buf][k][ty * 8];
        *(float4*)&av[4] = *(const float4*)&As[buf][k][ty * 8 + 4];
        float4 bq0 = *(const float4*)&Bs[buf][k][tx * 8];
        float4 bq1 = *(const float4*)&Bs[buf][k][tx * 8 + 4];
        u64 bp[4];
        bp[0] = pack2(bq0.x, bq0.y); bp[1] = pack2(bq0.z, bq0.w);
        bp[2] = pack2(bq1.x, bq1.y); bp[3] = pack2(bq1.z, bq1.w);
        #pragma unroll
        for (int i = 0; i < 8; i++) {
            u64 ad = pack2(av[i], av[i]);
            #pragma unroll
            for (int j = 0; j < 4; j++)
                acc[i][j] = fma2(ad, bp[j], acc[i][j]);
        }
    }

    #pragma unroll
    for (int i = 0; i < 8; i++) {
        int r = brow + ty * 8 + i;
        if (r >= M) continue;
        #pragma unroll
        for (int v = 0; v < 2; v++) {
            float4 o;
            unpack2(acc[i][v*2+0], o.x, o.y);
            unpack2(acc[i][v*2+1], o.z, o.w);
            *(float4*)(C + (size_t)r * ldc + bcol + tx * 8 + v * 4) = o;
        }
    }
}

// ---------------- fused C-GEMM: C = x@W1c, writes Ap=A0+C+b1, Bp=B0-C ---------
// 64x64x16, 4x4 microtile (FFMA2). M=E, N=512, K=128.
__global__ void __launch_bounds__(256) cgemm_fused(
    int M,
    const float* __restrict__ xin, int xld,
    const float* __restrict__ W1c,                 // 128x512 (= W1+1536*HID)
    const float* __restrict__ ABX,                 // A0 at +0, B0 at +512, ld NBIG
    const float* __restrict__ b1,
    float* __restrict__ Ap, float* __restrict__ Bp)
{
    const int BM = 64, BN = 64, BK = 16;
    __shared__ float As[2][BK][BM];
    __shared__ float Bs[2][BK][BN];
    const int tid  = threadIdx.x;
    const int brow = blockIdx.y * BM;
    const int bcol = blockIdx.x * BN;
    const int ar = tid >> 2, ac = (tid & 3) * 4;
    const int br = tid >> 4, bc = (tid & 15) * 4;
    const int tx = tid & 15, ty = tid >> 4;

    float4 areg = make_float4(0.f,0.f,0.f,0.f), breg;
    if (brow + ar < M) areg = *(const float4*)(xin + (size_t)(brow + ar) * xld + ac);
    breg = *(const float4*)(W1c + (size_t)br * HID + bcol + bc);
    As[0][ac+0][ar] = areg.x; As[0][ac+1][ar] = areg.y; As[0][ac+2][ar] = areg.z; As[0][ac+3][ar] = areg.w;
    *(float4*)&Bs[0][br][bc] = breg;
    __syncthreads();

    u64 acc[4][2];
    #pragma unroll
    for (int i = 0; i < 4; i++) { acc[i][0] = 0ull; acc[i][1] = 0ull; }

    int buf = 0;
    for (int k0 = BK; k0 < NL; k0 += BK) {
        areg = make_float4(0.f,0.f,0.f,0.f);
        if (brow + ar < M) areg = *(const float4*)(xin + (size_t)(brow + ar) * xld + k0 + ac);
        breg = *(const float4*)(W1c + (size_t)(k0 + br) * HID + bcol + bc);
        #pragma unroll
        for (int k = 0; k < BK; k++) {
            float av[4];
            *(float4*)av = *(const float4*)&As[buf][k][ty * 4];
            float4 bq = *(const float4*)&Bs[buf][k][tx * 4];
            u64 bp0 = pack2(bq.x, bq.y), bp1 = pack2(bq.z, bq.w);
            #pragma unroll
            for (int i = 0; i < 4; i++) {
                u64 ad = pack2(av[i], av[i]);
                acc[i][0] = fma2(ad, bp0, acc[i][0]);
                acc[i][1] = fma2(ad, bp1, acc[i][1]);
            }
        }
        int nb = buf ^ 1;
        As[nb][ac+0][ar] = areg.x; As[nb][ac+1][ar] = areg.y; As[nb][ac+2][ar] = areg.z; As[nb][ac+3][ar] = areg.w;
        *(float4*)&Bs[nb][br][bc] = breg;
        __syncthreads();
        buf = nb;
    }
    #pragma unroll
    for (int k = 0; k < BK; k++) {
        float av[4];
        *(float4*)av = *(const float4*)&As[buf][k][ty * 4];
        float4 bq = *(const float4*)&Bs[buf][k][tx * 4];
        u64 bp0 = pack2(bq.x, bq.y), bp1 = pack2(bq.z, bq.w);
        #pragma unroll
        for (int i = 0; i < 4; i++) {
            u64 ad = pack2(av[i], av[i]);
            acc[i][0] = fma2(ad, bp0, acc[i][0]);
            acc[i][1] = fma2(ad, bp1, acc[i][1]);
        }
    }

    int cc = bcol + tx * 4;
    float4 b1v = *(const float4*)(b1 + cc);
    #pragma unroll
    for (int i = 0; i < 4; i++) {
        int r = brow + ty * 4 + i;
        if (r >= M) continue;
        float c0, c1, c2, c3;
        unpack2(acc[i][0], c0, c1);
        unpack2(acc[i][1], c2, c3);
        float4 a0v = *(const float4*)(ABX + (size_t)r * NBIG + cc);
        float4 b0v = *(const float4*)(ABX + (size_t)r * NBIG + 512 + cc);
        float4 oa, ob;
        oa.x = a0v.x + c0 + b1v.x; ob.x = b0v.x - c0;
        oa.y = a0v.y + c1 + b1v.y; ob.y = b0v.y - c1;
        oa.z = a0v.z + c2 + b1v.z; ob.z = b0v.z - c2;
        oa.w = a0v.w + c3 + b1v.w; ob.w = b0v.w - c3;
        *(float4*)(Ap + (size_t)r * HID + cc) = oa;
        *(float4*)(Bp + (size_t)r * HID + cc) = ob;
    }
}

// ---------------- fused update GEMM: x_out = relu(Z@Wcat), Z built on the fly -
__device__ __forceinline__ float4 z_load(
    const float* __restrict__ xin, int xld,
    const float* __restrict__ sintra, const float* __restrict__ sinter,
    const float* __restrict__ cintra, const float* __restrict__ cinter,
    int r, int kg)
{
    int seg = kg >> 7, d = kg & 127;
    if (seg == 0) {
        return *(const float4*)(xin + (size_t)r * xld + d);
    } else if (seg == 1) {
        float4 s = *(const float4*)(sintra + (size_t)r * NL + d);
        float4 xv = *(const float4*)(xin + (size_t)r * xld + d);
        float rc = 0.7f / (cintra[r] + 1.0f);
        return make_float4((s.x + xv.x) * rc, (s.y + xv.y) * rc,
                           (s.z + xv.z) * rc, (s.w + xv.w) * rc);
    } else {
        float4 s = *(const float4*)(sinter + (size_t)r * NL + d);
        float rc = 0.3f / fmaxf(cinter[r], 1.0f);
        return make_float4(s.x * rc, s.y * rc, s.z * rc, s.w * rc);
    }
}

__global__ void __launch_bounds__(256) upd_fused(
    int M,
    const float* __restrict__ xin, int xld,
    const float* __restrict__ sintra, const float* __restrict__ sinter,
    const float* __restrict__ cintra, const float* __restrict__ cinter,
    const float* __restrict__ Wcat,                // 384x128
    float* __restrict__ xout)                      // ld NL
{
    const int BM = 64, BN = 64, BK = 16, KTOT = 3 * NL;
    __shared__ float As[2][BK][BM];
    __shared__ float Bs[2][BK][BN];
    const int tid  = threadIdx.x;
    const int brow = blockIdx.y * BM;
    const int bcol = blockIdx.x * BN;
    const int ar = tid >> 2, ac = (tid & 3) * 4;
    const int br = tid >> 4, bc = (tid & 15) * 4;
    const int tx = tid & 15, ty = tid >> 4;

    float4 areg = make_float4(0.f,0.f,0.f,0.f), breg;
    if (brow + ar < M) areg = z_load(xin, xld, sintra, sinter, cintra, cinter, brow + ar, ac);
    breg = *(const float4*)(Wcat + (size_t)br * NL + bcol + bc);
    As[0][ac+0][ar] = areg.x; As[0][ac+1][ar] = areg.y; As[0][ac+2][ar] = areg.z; As[0][ac+3][ar] = areg.w;
    *(float4*)&Bs[0][br][bc] = breg;
    __syncthreads();

    u64 acc[4][2];
    #pragma unroll
    for (int i = 0; i < 4; i++) { acc[i][0] = 0ull; acc[i][1] = 0ull; }

    int buf = 0;
    for (int k0 = BK; k0 < KTOT; k0 += BK) {
        areg = make_float4(0.f,0.f,0.f,0.f);
        if (brow + ar < M) areg = z_load(xin, xld, sintra, sinter, cintra, cinter, brow + ar, k0 + ac);
        breg = *(const float4*)(Wcat + (size_t)(k0 + br) * NL + bcol + bc);
        #pragma unroll
        for (int k = 0; k < BK; k++) {
            float av[4];
            *(float4*)av = *(const float4*)&As[buf][k][ty * 4];
            float4 bq = *(const float4*)&Bs[buf][k][tx * 4];
            u64 bp0 = pack2(bq.x, bq.y), bp1 = pack2(bq.z, bq.w);
            #pragma unroll
            for (int i = 0; i < 4; i++) {
                u64 ad = pack2(av[i], av[i]);
                acc[i][0] = fma2(ad, bp0, acc[i][0]);
                acc[i][1] = fma2(ad, bp1, acc[i][1]);
            }
        }
        int nb = buf ^ 1;
        As[nb][ac+0][ar] = areg.x; As[nb][ac+1][ar] = areg.y; As[nb][ac+2][ar] = areg.z; As[nb][ac+3][ar] = areg.w;
        *(float4*)&Bs[nb][br][bc] = breg;
        __syncthreads();
        buf = nb;
    }
    #pragma unroll
    for (int k = 0; k < BK; k++) {
        float av[4];
        *(float4*)av = *(const float4*)&As[buf][k][ty * 4];
        float4 bq = *(const float4*)&Bs[buf][k][tx * 4];
        u64 bp0 = pack2(bq.x, bq.y), bp1 = pack2(bq.z, bq.w);
        #pragma unroll
        for (int i = 0; i < 4; i++) {
            u64 ad = pack2(av[i], av[i]);
            acc[i][0] = fma2(ad, bp0, acc[i][0]);
            acc[i][1] = fma2(ad, bp1, acc[i][1]);
        }
    }

    #pragma unroll
    for (int i = 0; i < 4; i++) {
        int r = brow + ty * 4 + i;
        if (r >= M) continue;
        float4 o;
        unpack2(acc[i][0], o.x, o.y);
        unpack2(acc[i][1], o.z, o.w);
        o.x = fmaxf(o.x, 0.f); o.y = fmaxf(o.y, 0.f);
        o.z = fmaxf(o.z, 0.f); o.w = fmaxf(o.w, 0.f);
        *(float4*)(xout + (size_t)r * NL + bcol + tx * 4) = o;
    }
}

// ---------------- per-pair: logits, CE, masks, scatter; zero other phase ------
__global__ void __launch_bounds__(256) pair_kernel(
    const float* __restrict__ Ap, const float* __restrict__ Bp,
    const float* __restrict__ xin, int xld,
    const float* __restrict__ W2, const float* __restrict__ b2,
    const int* __restrict__ pair1, const int* __restrict__ pair2,
    const int* __restrict__ rtype, const int* __restrict__ targ,
    float* sintra, float* sinter, float* cintra, float* cinter,
    float* si_o, float* se_o, float* ci_o, float* ce_o,
    float* lossacc, float* logits_out, int P, int E)
{
    __shared__ float W2s0[HID], W2s1[HID], W2s2[HID];
    __shared__ float b2s[CLS];
    __shared__ float ce_s[8];
    int tid = threadIdx.x;
    for (int i = tid; i < HID; i += 256) {
        W2s0[i] = W2[i * 3 + 0];
        W2s1[i] = W2[i * 3 + 1];
        W2s2[i] = W2[i * 3 + 2];
    }
    if (tid < CLS) b2s[tid] = b2[tid];

    // fused zeroing of the OTHER phase's segment buffers (disjoint memory)
    {
        long idx = (long)blockIdx.x * 256 + tid;
        long stride = (long)gridDim.x * 256;
        for (long i = idx; i < (long)E * NL; i += stride) { si_o[i] = 0.f; se_o[i] = 0.f; }
        for (long i = idx; i < E; i += stride) { ci_o[i] = 0.f; ce_o[i] = 0.f; }
    }
    __syncthreads();

    int warp = tid >> 5, lane = tid & 31;
    int p = blockIdx.x * 8 + warp;
    float ce = 0.f;
    if (p < P) {
        int p1 = pair1[p], p2 = pair2[p];
        const float4* a4 = (const float4*)(Ap + (size_t)p1 * HID);
        const float4* b4 = (const float4*)(Bp + (size_t)p2 * HID);
        float a0 = 0.f, a1 = 0.f, a2 = 0.f;
        #pragma unroll
        for (int j = 0; j < 4; j++) {
            int i4 = j * 32 + lane;            // float4 index 0..127
            float4 av = a4[i4], bv = b4[i4];
            float4 h;
            h.x = fmaxf(av.x + bv.x, 0.f);
            h.y = fmaxf(av.y + bv.y, 0.f);
            h.z = fmaxf(av.z + bv.z, 0.f);
            h.w = fmaxf(av.w + bv.w, 0.f);
            int base = i4 * 4;
            float4 w0 = *(const float4*)&W2s0[base];
            float4 w1 = *(const float4*)&W2s1[base];
            float4 w2 = *(const float4*)&W2s2[base];
            a0 = fmaf(h.x, w0.x, fmaf(h.y, w0.y, fmaf(h.z, w0.z, fmaf(h.w, w0.w, a0))));
            a1 = fmaf(h.x, w1.x, fmaf(h.y, w1.y, fmaf(h.z, w1.z, fmaf(h.w, w1.w, a1))));
            a2 = fmaf(h.x, w2.x, fmaf(h.y, w2.y, fmaf(h.z, w2.z, fmaf(h.w, w2.w, a2))));
        }
        #pragma unroll
        for (int o = 16; o; o >>= 1) {
            a0 += __shfl_xor_sync(0xffffffffu, a0, o);
            a1 += __shfl_xor_sync(0xffffffffu, a1, o);
            a2 += __shfl_xor_sync(0xffffffffu, a2, o);
        }
        float l0 = a0 + b2s[0], l1 = a1 + b2s[1], l2 = a2 + b2s[2];
        float m = fmaxf(l0, fmaxf(l1, l2));
        float s = expf(l0 - m) + expf(l1 - m) + expf(l2 - m);
        int tg = targ[p];
        float lt = (tg == 0) ? l0 : ((tg == 1) ? l1 : l2);
        ce = logf(s) + m - lt;
        if (logits_out != nullptr && lane == 0) {
            logits_out[(size_t)p * 3 + 0] = l0;
            logits_out[(size_t)p * 3 + 1] = l1;
            logits_out[(size_t)p * 3 + 2] = l2;
        }
        int argm = 0; float mm = l0;
        if (l1 > mm) { mm = l1; argm = 1; }
        if (l2 > mm) { mm = l2; argm = 2; }
        bool conf = (1.0f / s) > 0.3f;
        int rt = rtype[p];
        if (conf && (argm == 1 || argm == 2)) {
            bool srcIs1 = (argm == 1);
            int src = srcIs1 ? p1 : p2;
            int dst = srcIs1 ? p2 : p1;
            float* sb = (rt == 0) ? sintra : sinter;
            float* cb = (rt == 0) ? cintra : cinter;
            const float* xs = xin + (size_t)src * xld;
            #pragma unroll
            for (int j = 0; j < NL / 32; j++) {
                int d = j * 32 + lane;
                atomicAdd(&sb[(size_t)dst * NL + d], xs[d]);
            }
            if (lane == 0) atomicAdd(&cb[dst], 1.0f);
        }
    }
    if (lane == 0) ce_s[warp] = (p < P) ? ce : 0.f;
    __syncthreads();
    if (tid == 0) {
        float t = ce_s[0] + ce_s[1] + ce_s[2] + ce_s[3]
                + ce_s[4] + ce_s[5] + ce_s[6] + ce_s[7];
        atomicAdd(lossacc, t);
    }
}

__global__ void final_loss_kernel(const float* lp, float* out, int P)
{
    out[0] = (lp[0] + lp[1] * 0.5f + lp[2] * (1.0f / 3.0f)) / (float)P;
}

// ---------------- launch ------------------------------------------------------
extern "C" void kernel_launch(void* const* d_in, const int* in_sizes, int n_in,
                              void* d_out, int out_size)
{
    const float* sent   = (const float*)d_in[0];
    const float* Wproj  = (const float*)d_in[1];
    const float* W1     = (const float*)d_in[2];
    const float* b1     = (const float*)d_in[3];
    const float* W2     = (const float*)d_in[4];
    const float* b2     = (const float*)d_in[5];
    const float* Wself  = (const float*)d_in[6];
    const float* Wintra = (const float*)d_in[7];
    const float* Winter = (const float*)d_in[8];
    const int* esent  = (const int*)d_in[9];
    const int* estart = (const int*)d_in[10];
    const int* elen   = (const int*)d_in[11];
    const int* pair1  = (const int*)d_in[12];
    const int* pair2  = (const int*)d_in[13];
    const int* rtype  = (const int*)d_in[14];
    const int* targ   = (const int*)d_in[15];
    float* out = (float*)d_out;

    int E = in_sizes[9];
    int P = in_sizes[12];
    if (E > E_MAX) E = E_MAX;
    if (P > P_MAX) P = P_MAX;

    float *eemb, *Wbig, *ABX, *Ap, *Bp, *Wcat, *lp;
    float *xb[2], *si[2], *se[2], *ci[2], *ce[2];
    cudaGetSymbolAddress((void**)&eemb, g_eemb);
    cudaGetSymbolAddress((void**)&Wbig, g_Wbig);
    cudaGetSymbolAddress((void**)&ABX,  g_ABX);
    cudaGetSymbolAddress((void**)&Ap,   g_Ap);
    cudaGetSymbolAddress((void**)&Bp,   g_Bp);
    cudaGetSymbolAddress((void**)&Wcat, g_Wcat);
    cudaGetSymbolAddress((void**)&lp,   g_losspart);
    {
        float* base;
        cudaGetSymbolAddress((void**)&base, g_xbuf);
        xb[0] = base; xb[1] = base + E_MAX * NL;
        cudaGetSymbolAddress((void**)&base, g_sintra);
        si[0] = base; si[1] = base + E_MAX * NL;
        cudaGetSymbolAddress((void**)&base, g_sinter);
        se[0] = base; se[1] = base + E_MAX * NL;
        cudaGetSymbolAddress((void**)&base, g_cintra);
        ci[0] = base; ci[1] = base + E_MAX;
        cudaGetSymbolAddress((void**)&base, g_cinter);
        ce[0] = base; ce[1] = base + E_MAX;
    }

    int loff = out_size - 3 * P;
    if (loff < 0) loff = 0;
    float* logits_out = out + loff;

    // 1) extract + prep
    extract_kernel<<<E, D_DIM / 4>>>(sent, esent, estart, elen, eemb);
    {
        long tot = (long)D_DIM * NBIG + 3 * NL * NL + (long)E * NL + E + 4;
        prep_kernel<<<(int)((tot + 255) / 256), 256>>>(W1, Wproj, Wself, Wintra, Winter, E);
    }

    // 2) one big GEMM: ABX = eemb @ Wbig (2000 x 1152 x 768)
    {
        dim3 g(NBIG / 128, (E + 127) / 128);
        sgemm_big<<<g, 256>>>(E, NBIG, D_DIM, eemb, D_DIM, Wbig, NBIG, ABX, NBIG);
    }

    // 3) three iterations
    const float* W1c = W1 + (size_t)1536 * HID;
    for (int it = 0; it < 3; it++) {
        int ph = it & 1, po = ph ^ 1;
        const float* xin = (it == 0) ? (ABX + 1024) : xb[(it - 1) & 1];
        int xld = (it == 0) ? NBIG : NL;
        float* xout = xb[it & 1];

        {   // Ap/Bp fold GEMM (2000 x 512 x 128)
            dim3 g(HID / 64, (E + 63) / 64);
            cgemm_fused<<<g, 256>>>(E, xin, xld, W1c, ABX, b1, Ap, Bp);
        }
        pair_kernel<<<(P + 7) / 8, 256>>>(Ap, Bp, xin, xld, W2, b2,
                                          pair1, pair2, rtype, targ,
                                          si[ph], se[ph], ci[ph], ce[ph],
                                          si[po], se[po], ci[po], ce[po],
                                          lp + it, (it == 2) ? logits_out : nullptr, P, E);
        {   // x_out = relu(Z @ Wcat)  (2000 x 128 x 384), Z built on the fly
            dim3 g(NL / 64, (E + 63) / 64);
            upd_fused<<<g, 256>>>(E, xin, xld,
                                  si[ph], se[ph], ci[ph], ce[ph],
                                  Wcat, xout);
        }
    }

    // 4) loss
    final_loss_kernel<<<1, 1>>>(lp, out, P);
}

// round 6
// speedup vs baseline: 3.1964x; 1.0704x over previous
#include <cuda_runtime.h>
#include <cuda_bf16.h>
#include <math.h>
#include <stdint.h>

#define NSENT 64
#define S_LEN 512
#define D_DIM 768
#define NL    128
#define HID   512
#define CLS   3
#define E_MAX 2000
#define P_MAX 20000
#define NBIG  1152            // 512(A0) + 512(B0) + 128(x0)
#define KCAT  2304            // 3 * 768 (bf16x3 split along K)
#define BKH   32              // K-halves per smem chunk
#define NCH   (KCAT / BKH)    // 72

// ---------------- static device scratch ----------------
__device__ __nv_bfloat16 g_Acat[E_MAX * KCAT];   // [hi | lo | hi] along K
__device__ __nv_bfloat16 g_Bcat[NBIG * KCAT];    // W^T, [hi | hi | lo] along K
__device__ float g_ABX  [E_MAX * NBIG];          // [A0 | B0 | x0]
__device__ float g_Ap   [E_MAX * HID];           // A0 + C + b1
__device__ float g_Bp   [E_MAX * HID];           // B0 - C
__device__ float g_xbuf [2][E_MAX * NL];
__device__ float g_sintra[2][E_MAX * NL];
__device__ float g_sinter[2][E_MAX * NL];
__device__ float g_cintra[2][E_MAX];
__device__ float g_cinter[2][E_MAX];
__device__ float g_Wcat [3 * NL * NL];
__device__ float g_losspart[4];

// ---------------- warp-mma helpers (portable sm_80+ ISA) ----------------
__device__ __forceinline__ uint32_t smem_u32(const void* p) {
    uint32_t a;
    asm("{ .reg .u64 t; cvta.to.shared.u64 t, %1; cvt.u32.u64 %0, t; }"
        : "=r"(a) : "l"(p));
    return a;
}
__device__ __forceinline__ void ldmatrix_x4(uint32_t* r, uint32_t addr) {
    asm volatile("ldmatrix.sync.aligned.m8n8.x4.shared.b16 {%0,%1,%2,%3}, [%4];"
                 : "=r"(r[0]), "=r"(r[1]), "=r"(r[2]), "=r"(r[3]) : "r"(addr));
}
__device__ __forceinline__ void ldmatrix_x2(uint32_t* r, uint32_t addr) {
    asm volatile("ldmatrix.sync.aligned.m8n8.x2.shared.b16 {%0,%1}, [%2];"
                 : "=r"(r[0]), "=r"(r[1]) : "r"(addr));
}
__device__ __forceinline__ void mma16816(float* d, const uint32_t* a, const uint32_t* b) {
    asm volatile("mma.sync.aligned.m16n8k16.row.col.f32.bf16.bf16.f32 "
                 "{%0,%1,%2,%3}, {%4,%5,%6,%7}, {%8,%9}, {%0,%1,%2,%3};"
                 : "+f"(d[0]), "+f"(d[1]), "+f"(d[2]), "+f"(d[3])
                 : "r"(a[0]), "r"(a[1]), "r"(a[2]), "r"(a[3]), "r"(b[0]), "r"(b[1]));
}

// ---------------- event extraction -> bf16x3 split rows of Acat ---------------
__global__ void extract_kernel(const float* __restrict__ sent,
                               const int* __restrict__ esent,
                               const int* __restrict__ estart,
                               const int* __restrict__ elen,
                               __nv_bfloat16* __restrict__ Acat)
{
    int e = blockIdx.x;
    int len = elen[e] + 1;
    int st  = estart[e];
    int snt = esent[e];
    float inv = 1.0f / (float)len;
    const float4* base = (const float4*)(sent + (size_t)snt * S_LEN * D_DIM);
    int d4 = threadIdx.x;              // blockDim = 192
    float4 acc = make_float4(0.f, 0.f, 0.f, 0.f);
    for (int o = 0; o < len; o++) {
        int idx = st + o; if (idx > S_LEN - 1) idx = S_LEN - 1;
        float4 v = base[(size_t)idx * (D_DIM / 4) + d4];
        acc.x += v.x; acc.y += v.y; acc.z += v.z; acc.w += v.w;
    }
    acc.x *= inv; acc.y *= inv; acc.z *= inv; acc.w *= inv;
    float vv[4] = {acc.x, acc.y, acc.z, acc.w};
    ushort4 hi4, lo4;
    unsigned short h[4], l[4];
    #pragma unroll
    for (int j = 0; j < 4; j++) {
        __nv_bfloat16 hb = __float2bfloat16_rn(vv[j]);
        __nv_bfloat16 lb = __float2bfloat16_rn(vv[j] - __bfloat162float(hb));
        h[j] = __bfloat16_as_ushort(hb);
        l[j] = __bfloat16_as_ushort(lb);
    }
    hi4.x = h[0]; hi4.y = h[1]; hi4.z = h[2]; hi4.w = h[3];
    lo4.x = l[0]; lo4.y = l[1]; lo4.z = l[2]; lo4.w = l[3];
    ushort4* row = (ushort4*)(Acat + (size_t)e * KCAT);
    row[d4]                 = hi4;   // K block 0: hi
    row[(768 / 4) + d4]     = lo4;   // K block 1: lo
    row[(1536 / 4) + d4]    = hi4;   // K block 2: hi
}

// ---------------- W transpose + bf16x3 split: Bcat[n][k] ----------------------
__global__ void wtrans_kernel(const float* __restrict__ W1,
                              const float* __restrict__ Wproj,
                              __nv_bfloat16* __restrict__ Bcat)
{
    __shared__ float t[32][33];
    int n0 = blockIdx.x * 32, k0 = blockIdx.y * 32;
    int tx = threadIdx.x, ty = threadIdx.y;   // block (32, 8)
    #pragma unroll
    for (int i = 0; i < 32; i += 8) {
        int k = k0 + ty + i, n = n0 + tx;
        float v;
        if (n < 512)        v = W1[(size_t)k * HID + n];
        else if (n < 1024)  v = W1[(size_t)(768 + k) * HID + (n - 512)];
        else                v = Wproj[(size_t)k * NL + (n - 1024)];
        t[ty + i][tx] = v;
    }
    __syncthreads();
    #pragma unroll
    for (int i = 0; i < 32; i += 8) {
        int n = n0 + ty + i, k = k0 + tx;
        float v = t[tx][ty + i];
        __nv_bfloat16 hb = __float2bfloat16_rn(v);
        __nv_bfloat16 lb = __float2bfloat16_rn(v - __bfloat162float(hb));
        Bcat[(size_t)n * KCAT + k]        = hb;  // block 0: hi
        Bcat[(size_t)n * KCAT + 768 + k]  = hb;  // block 1: hi
        Bcat[(size_t)n * KCAT + 1536 + k] = lb;  // block 2: lo
    }
}

// ---------------- prep: Wcat stack + zero phase-0 + loss ----------------------
__global__ void prep_kernel(const float* __restrict__ Wself,
                            const float* __restrict__ Wintra,
                            const float* __restrict__ Winter,
                            int E)
{
    long i = (long)blockIdx.x * blockDim.x + threadIdx.x;
    const long N_WCAT = 3 * NL * NL;
    if (i < N_WCAT) {
        int k = (int)(i / NL), d = (int)(i % NL);
        const float* src = (k < NL) ? Wself : ((k < 2 * NL) ? Wintra : Winter);
        g_Wcat[i] = src[(k % NL) * NL + d];
        return;
    }
    i -= N_WCAT;
    if (i < (long)E * NL) { g_sintra[0][i] = 0.f; g_sinter[0][i] = 0.f; return; }
    i -= (long)E * NL;
    if (i < E) { g_cintra[0][i] = 0.f; g_cinter[0][i] = 0.f; return; }
    i -= E;
    if (i < 4) g_losspart[i] = 0.f;
}

// ---------------- warp-mma bf16x3 GEMM: ABX = Acat @ Bcat^T (fp32 accum) ------
// grid (9, 16), 256 threads = 8 warps of 64x32. 72 chunks of K=32, dbl-buffered.
__global__ void __launch_bounds__(256) mma_gemm(
    int E_,
    const __nv_bfloat16* __restrict__ Acat,
    const __nv_bfloat16* __restrict__ Bcat,
    float* __restrict__ Cout)
{
    __shared__ __align__(16) __nv_bfloat16 As[2][128][BKH + 8];
    __shared__ __align__(16) __nv_bfloat16 Bs[2][128][BKH + 8];
    const int tid  = threadIdx.x;
    const int lane = tid & 31, wid = tid >> 5;
    const int wm = (wid & 1) * 64;         // warp M offset
    const int wn = (wid >> 1) * 32;        // warp N offset
    const int brow = blockIdx.y * 128;
    const int bcol = blockIdx.x * 128;

    const int lrow = tid >> 1;             // 0..127
    const int lseg = (tid & 1) * 16;       // halves offset: 0 or 16

    float acc[4][4][4];
    #pragma unroll
    for (int mi = 0; mi < 4; mi++)
        #pragma unroll
        for (int ni = 0; ni < 4; ni++)
            #pragma unroll
            for (int r = 0; r < 4; r++) acc[mi][ni][r] = 0.f;

    uint4 pa0, pa1, pb0, pb1;
    auto gload = [&](int c) {
        int gr = brow + lrow;
        if (gr < E_) {
            const __nv_bfloat16* ar = Acat + (size_t)gr * KCAT + c * BKH + lseg;
            pa0 = *(const uint4*)(ar);
            pa1 = *(const uint4*)(ar + 8);
        } else {
            pa0 = make_uint4(0u, 0u, 0u, 0u); pa1 = pa0;
        }
        const __nv_bfloat16* br = Bcat + (size_t)(bcol + lrow) * KCAT + c * BKH + lseg;
        pb0 = *(const uint4*)(br);
        pb1 = *(const uint4*)(br + 8);
    };
    auto sstore = [&](int s) {
        *(uint4*)&As[s][lrow][lseg]     = pa0;
        *(uint4*)&As[s][lrow][lseg + 8] = pa1;
        *(uint4*)&Bs[s][lrow][lseg]     = pb0;
        *(uint4*)&Bs[s][lrow][lseg + 8] = pb1;
    };

    gload(0);
    sstore(0);
    __syncthreads();

    for (int c = 0; c < NCH; c++) {
        int s = c & 1;
        if (c + 1 < NCH) gload(c + 1);

        #pragma unroll
        for (int kk = 0; kk < 2; kk++) {
            uint32_t af[4][4], bf2[4][2];
            #pragma unroll
            for (int mi = 0; mi < 4; mi++) {
                uint32_t addr = smem_u32(&As[s][wm + mi * 16 + (lane & 15)]
                                            [kk * 16 + (lane >> 4) * 8]);
                ldmatrix_x4(af[mi], addr);
            }
            #pragma unroll
            for (int ni = 0; ni < 4; ni++) {
                uint32_t addr = smem_u32(&Bs[s][wn + ni * 8 + (lane & 7)]
                                            [kk * 16 + ((lane >> 3) & 1) * 8]);
                ldmatrix_x2(bf2[ni], addr);
            }
            #pragma unroll
            for (int mi = 0; mi < 4; mi++)
                #pragma unroll
                for (int ni = 0; ni < 4; ni++)
                    mma16816(acc[mi][ni], af[mi], bf2[ni]);
        }

        if (c + 1 < NCH) sstore(s ^ 1);
        __syncthreads();
    }

    // epilogue: d[m][n]; thread holds (row lane>>2 [+8], cols 2*(lane&3)+{0,1})
    #pragma unroll
    for (int mi = 0; mi < 4; mi++) {
        int m0 = brow + wm + mi * 16 + (lane >> 2);
        #pragma unroll
        for (int ni = 0; ni < 4; ni++) {
            int n = bcol + wn + ni * 8 + (lane & 3) * 2;
            if (m0 < E_)
                *(float2*)(Cout + (size_t)m0 * NBIG + n) =
                    make_float2(acc[mi][ni][0], acc[mi][ni][1]);
            if (m0 + 8 < E_)
                *(float2*)(Cout + (size_t)(m0 + 8) * NBIG + n) =
                    make_float2(acc[mi][ni][2], acc[mi][ni][3]);
        }
    }
}

// ---------------- fused C-GEMM: C = x@W1c, writes Ap=A0+C+b1, Bp=B0-C ---------
// 64x64x16, 4x4 microtile (scalar FFMA). M=E, N=512, K=128.
__global__ void __launch_bounds__(256) cgemm_fused(
    int M,
    const float* __restrict__ xin, int xld,
    const float* __restrict__ W1c,                 // 128x512 (= W1+1536*HID)
    const float* __restrict__ ABX,                 // A0 at +0, B0 at +512, ld NBIG
    const float* __restrict__ b1,
    float* __restrict__ Ap, float* __restrict__ Bp)
{
    const int BM = 64, BN = 64, BK = 16;
    __shared__ float As[2][BK][BM];
    __shared__ float Bs[2][BK][BN];
    const int tid  = threadIdx.x;
    const int brow = blockIdx.y * BM;
    const int bcol = blockIdx.x * BN;
    const int ar = tid >> 2, ac = (tid & 3) * 4;
    const int br = tid >> 4, bc = (tid & 15) * 4;
    const int tx = tid & 15, ty = tid >> 4;

    float4 areg = make_float4(0.f,0.f,0.f,0.f), breg;
    if (brow + ar < M) areg = *(const float4*)(xin + (size_t)(brow + ar) * xld + ac);
    breg = *(const float4*)(W1c + (size_t)br * HID + bcol + bc);
    As[0][ac+0][ar] = areg.x; As[0][ac+1][ar] = areg.y; As[0][ac+2][ar] = areg.z; As[0][ac+3][ar] = areg.w;
    *(float4*)&Bs[0][br][bc] = breg;
    __syncthreads();

    float acc[4][4];
    #pragma unroll
    for (int i = 0; i < 4; i++)
        #pragma unroll
        for (int j = 0; j < 4; j++) acc[i][j] = 0.f;

    int buf = 0;
    for (int k0 = BK; k0 < NL; k0 += BK) {
        areg = make_float4(0.f,0.f,0.f,0.f);
        if (brow + ar < M) areg = *(const float4*)(xin + (size_t)(brow + ar) * xld + k0 + ac);
        breg = *(const float4*)(W1c + (size_t)(k0 + br) * HID + bcol + bc);
        #pragma unroll
        for (int k = 0; k < BK; k++) {
            float av[4], bv[4];
            *(float4*)av = *(const float4*)&As[buf][k][ty * 4];
            *(float4*)bv = *(const float4*)&Bs[buf][k][tx * 4];
            #pragma unroll
            for (int i = 0; i < 4; i++)
                #pragma unroll
                for (int j = 0; j < 4; j++)
                    acc[i][j] = fmaf(av[i], bv[j], acc[i][j]);
        }
        int nb = buf ^ 1;
        As[nb][ac+0][ar] = areg.x; As[nb][ac+1][ar] = areg.y; As[nb][ac+2][ar] = areg.z; As[nb][ac+3][ar] = areg.w;
        *(float4*)&Bs[nb][br][bc] = breg;
        __syncthreads();
        buf = nb;
    }
    #pragma unroll
    for (int k = 0; k < BK; k++) {
        float av[4], bv[4];
        *(float4*)av = *(const float4*)&As[buf][k][ty * 4];
        *(float4*)bv = *(const float4*)&Bs[buf][k][tx * 4];
        #pragma unroll
        for (int i = 0; i < 4; i++)
            #pragma unroll
            for (int j = 0; j < 4; j++)
                acc[i][j] = fmaf(av[i], bv[j], acc[i][j]);
    }

    int cc = bcol + tx * 4;
    float4 b1v = *(const float4*)(b1 + cc);
    #pragma unroll
    for (int i = 0; i < 4; i++) {
        int r = brow + ty * 4 + i;
        if (r >= M) continue;
        float4 a0v = *(const float4*)(ABX + (size_t)r * NBIG + cc);
        float4 b0v = *(const float4*)(ABX + (size_t)r * NBIG + 512 + cc);
        float4 oa, ob;
        oa.x = a0v.x + acc[i][0] + b1v.x; ob.x = b0v.x - acc[i][0];
        oa.y = a0v.y + acc[i][1] + b1v.y; ob.y = b0v.y - acc[i][1];
        oa.z = a0v.z + acc[i][2] + b1v.z; ob.z = b0v.z - acc[i][2];
        oa.w = a0v.w + acc[i][3] + b1v.w; ob.w = b0v.w - acc[i][3];
        *(float4*)(Ap + (size_t)r * HID + cc) = oa;
        *(float4*)(Bp + (size_t)r * HID + cc) = ob;
    }
}

// ---------------- fused update GEMM: x_out = relu(Z@Wcat), Z built on the fly -
__device__ __forceinline__ float4 z_load(
    const float* __restrict__ xin, int xld,
    const float* __restrict__ sintra, const float* __restrict__ sinter,
    const float* __restrict__ cintra, const float* __restrict__ cinter,
    int r, int kg)
{
    int seg = kg >> 7, d = kg & 127;
    if (seg == 0) {
        return *(const float4*)(xin + (size_t)r * xld + d);
    } else if (seg == 1) {
        float4 s = *(const float4*)(sintra + (size_t)r * NL + d);
        float4 xv = *(const float4*)(xin + (size_t)r * xld + d);
        float rc = 0.7f / (cintra[r] + 1.0f);
        return make_float4((s.x + xv.x) * rc, (s.y + xv.y) * rc,
                           (s.z + xv.z) * rc, (s.w + xv.w) * rc);
    } else {
        float4 s = *(const float4*)(sinter + (size_t)r * NL + d);
        float rc = 0.3f / fmaxf(cinter[r], 1.0f);
        return make_float4(s.x * rc, s.y * rc, s.z * rc, s.w * rc);
    }
}

__global__ void __launch_bounds__(256) upd_fused(
    int M,
    const float* __restrict__ xin, int xld,
    const float* __restrict__ sintra, const float* __restrict__ sinter,
    const float* __restrict__ cintra, const float* __restrict__ cinter,
    const float* __restrict__ Wcat,
    float* __restrict__ xout)
{
    const int BM = 64, BN = 64, BK = 16, KTOT = 3 * NL;
    __shared__ float As[2][BK][BM];
    __shared__ float Bs[2][BK][BN];
    const int tid  = threadIdx.x;
    const int brow = blockIdx.y * BM;
    const int bcol = blockIdx.x * BN;
    const int ar = tid >> 2, ac = (tid & 3) * 4;
    const int br = tid >> 4, bc = (tid & 15) * 4;
    const int tx = tid & 15, ty = tid >> 4;

    float4 areg = make_float4(0.f,0.f,0.f,0.f), breg;
    if (brow + ar < M) areg = z_load(xin, xld, sintra, sinter, cintra, cinter, brow + ar, ac);
    breg = *(const float4*)(Wcat + (size_t)br * NL + bcol + bc);
    As[0][ac+0][ar] = areg.x; As[0][ac+1][ar] = areg.y; As[0][ac+2][ar] = areg.z; As[0][ac+3][ar] = areg.w;
    *(float4*)&Bs[0][br][bc] = breg;
    __syncthreads();

    float acc[4][4];
    #pragma unroll
    for (int i = 0; i < 4; i++)
        #pragma unroll
        for (int j = 0; j < 4; j++) acc[i][j] = 0.f;

    int buf = 0;
    for (int k0 = BK; k0 < KTOT; k0 += BK) {
        areg = make_float4(0.f,0.f,0.f,0.f);
        if (brow + ar < M) areg = z_load(xin, xld, sintra, sinter, cintra, cinter, brow + ar, k0 + ac);
        breg = *(const float4*)(Wcat + (size_t)(k0 + br) * NL + bcol + bc);
        #pragma unroll
        for (int k = 0; k < BK; k++) {
            float av[4], bv[4];
            *(float4*)av = *(const float4*)&As[buf][k][ty * 4];
            *(float4*)bv = *(const float4*)&Bs[buf][k][tx * 4];
            #pragma unroll
            for (int i = 0; i < 4; i++)
                #pragma unroll
                for (int j = 0; j < 4; j++)
                    acc[i][j] = fmaf(av[i], bv[j], acc[i][j]);
        }
        int nb = buf ^ 1;
        As[nb][ac+0][ar] = areg.x; As[nb][ac+1][ar] = areg.y; As[nb][ac+2][ar] = areg.z; As[nb][ac+3][ar] = areg.w;
        *(float4*)&Bs[nb][br][bc] = breg;
        __syncthreads();
        buf = nb;
    }
    #pragma unroll
    for (int k = 0; k < BK; k++) {
        float av[4], bv[4];
        *(float4*)av = *(const float4*)&As[buf][k][ty * 4];
        *(float4*)bv = *(const float4*)&Bs[buf][k][tx * 4];
        #pragma unroll
        for (int i = 0; i < 4; i++)
            #pragma unroll
            for (int j = 0; j < 4; j++)
                acc[i][j] = fmaf(av[i], bv[j], acc[i][j]);
    }

    #pragma unroll
    for (int i = 0; i < 4; i++) {
        int r = brow + ty * 4 + i;
        if (r >= M) continue;
        float4 o;
        o.x = fmaxf(acc[i][0], 0.f); o.y = fmaxf(acc[i][1], 0.f);
        o.z = fmaxf(acc[i][2], 0.f); o.w = fmaxf(acc[i][3], 0.f);
        *(float4*)(xout + (size_t)r * NL + bcol + tx * 4) = o;
    }
}

// ---------------- per-pair: logits, CE, masks, scatter; zero other phase ------
__global__ void __launch_bounds__(256) pair_kernel(
    const float* __restrict__ Ap, const float* __restrict__ Bp,
    const float* __restrict__ xin, int xld,
    const float* __restrict__ W2, const float* __restrict__ b2,
    const int* __restrict__ pair1, const int* __restrict__ pair2,
    const int* __restrict__ rtype, const int* __restrict__ targ,
    float* sintra, float* sinter, float* cintra, float* cinter,
    float* si_o, float* se_o, float* ci_o, float* ce_o,
    float* lossacc, float* logits_out, int P, int E)
{
    __shared__ float W2s0[HID], W2s1[HID], W2s2[HID];
    __shared__ float b2s[CLS];
    __shared__ float ce_s[8];
    int tid = threadIdx.x;
    for (int i = tid; i < HID; i += 256) {
        W2s0[i] = W2[i * 3 + 0];
        W2s1[i] = W2[i * 3 + 1];
        W2s2[i] = W2[i * 3 + 2];
    }
    if (tid < CLS) b2s[tid] = b2[tid];

    {
        long idx = (long)blockIdx.x * 256 + tid;
        long stride = (long)gridDim.x * 256;
        for (long i = idx; i < (long)E * NL; i += stride) { si_o[i] = 0.f; se_o[i] = 0.f; }
        for (long i = idx; i < E; i += stride) { ci_o[i] = 0.f; ce_o[i] = 0.f; }
    }
    __syncthreads();

    int warp = tid >> 5, lane = tid & 31;
    int p = blockIdx.x * 8 + warp;
    float ce = 0.f;
    if (p < P) {
        int p1 = pair1[p], p2 = pair2[p];
        const float4* a4 = (const float4*)(Ap + (size_t)p1 * HID);
        const float4* b4 = (const float4*)(Bp + (size_t)p2 * HID);
        float a0 = 0.f, a1 = 0.f, a2 = 0.f;
        #pragma unroll
        for (int j = 0; j < 4; j++) {
            int i4 = j * 32 + lane;
            float4 av = a4[i4], bv = b4[i4];
            float4 h;
            h.x = fmaxf(av.x + bv.x, 0.f);
            h.y = fmaxf(av.y + bv.y, 0.f);
            h.z = fmaxf(av.z + bv.z, 0.f);
            h.w = fmaxf(av.w + bv.w, 0.f);
            int base = i4 * 4;
            float4 w0 = *(const float4*)&W2s0[base];
            float4 w1 = *(const float4*)&W2s1[base];
            float4 w2 = *(const float4*)&W2s2[base];
            a0 = fmaf(h.x, w0.x, fmaf(h.y, w0.y, fmaf(h.z, w0.z, fmaf(h.w, w0.w, a0))));
            a1 = fmaf(h.x, w1.x, fmaf(h.y, w1.y, fmaf(h.z, w1.z, fmaf(h.w, w1.w, a1))));
            a2 = fmaf(h.x, w2.x, fmaf(h.y, w2.y, fmaf(h.z, w2.z, fmaf(h.w, w2.w, a2))));
        }
        #pragma unroll
        for (int o = 16; o; o >>= 1) {
            a0 += __shfl_xor_sync(0xffffffffu, a0, o);
            a1 += __shfl_xor_sync(0xffffffffu, a1, o);
            a2 += __shfl_xor_sync(0xffffffffu, a2, o);
        }
        float l0 = a0 + b2s[0], l1 = a1 + b2s[1], l2 = a2 + b2s[2];
        float m = fmaxf(l0, fmaxf(l1, l2));
        float s = expf(l0 - m) + expf(l1 - m) + expf(l2 - m);
        int tg = targ[p];
        float lt = (tg == 0) ? l0 : ((tg == 1) ? l1 : l2);
        ce = logf(s) + m - lt;
        if (logits_out != nullptr && lane == 0) {
            logits_out[(size_t)p * 3 + 0] = l0;
            logits_out[(size_t)p * 3 + 1] = l1;
            logits_out[(size_t)p * 3 + 2] = l2;
        }
        int argm = 0; float mm = l0;
        if (l1 > mm) { mm = l1; argm = 1; }
        if (l2 > mm) { mm = l2; argm = 2; }
        bool conf = (1.0f / s) > 0.3f;
        int rt = rtype[p];
        if (conf && (argm == 1 || argm == 2)) {
            bool srcIs1 = (argm == 1);
            int src = srcIs1 ? p1 : p2;
            int dst = srcIs1 ? p2 : p1;
            float* sb = (rt == 0) ? sintra : sinter;
            float* cb = (rt == 0) ? cintra : cinter;
            const float* xs = xin + (size_t)src * xld;
            #pragma unroll
            for (int j = 0; j < NL / 32; j++) {
                int d = j * 32 + lane;
                atomicAdd(&sb[(size_t)dst * NL + d], xs[d]);
            }
            if (lane == 0) atomicAdd(&cb[dst], 1.0f);
        }
    }
    if (lane == 0) ce_s[warp] = (p < P) ? ce : 0.f;
    __syncthreads();
    if (tid == 0) {
        float t = ce_s[0] + ce_s[1] + ce_s[2] + ce_s[3]
                + ce_s[4] + ce_s[5] + ce_s[6] + ce_s[7];
        atomicAdd(lossacc, t);
    }
}

__global__ void final_loss_kernel(const float* lp, float* out, int P)
{
    out[0] = (lp[0] + lp[1] * 0.5f + lp[2] * (1.0f / 3.0f)) / (float)P;
}

// ---------------- launch ------------------------------------------------------
extern "C" void kernel_launch(void* const* d_in, const int* in_sizes, int n_in,
                              void* d_out, int out_size)
{
    const float* sent   = (const float*)d_in[0];
    const float* Wproj  = (const float*)d_in[1];
    const float* W1     = (const float*)d_in[2];
    const float* b1     = (const float*)d_in[3];
    const float* W2     = (const float*)d_in[4];
    const float* b2     = (const float*)d_in[5];
    const float* Wself  = (const float*)d_in[6];
    const float* Wintra = (const float*)d_in[7];
    const float* Winter = (const float*)d_in[8];
    const int* esent  = (const int*)d_in[9];
    const int* estart = (const int*)d_in[10];
    const int* elen   = (const int*)d_in[11];
    const int* pair1  = (const int*)d_in[12];
    const int* pair2  = (const int*)d_in[13];
    const int* rtype  = (const int*)d_in[14];
    const int* targ   = (const int*)d_in[15];
    float* out = (float*)d_out;

    int E = in_sizes[9];
    int P = in_sizes[12];
    if (E > E_MAX) E = E_MAX;
    if (P > P_MAX) P = P_MAX;

    __nv_bfloat16 *Acat, *Bcat;
    float *ABX, *Ap, *Bp, *Wcat, *lp;
    float *xb[2], *si[2], *se[2], *ci[2], *ce[2];
    cudaGetSymbolAddress((void**)&Acat, g_Acat);
    cudaGetSymbolAddress((void**)&Bcat, g_Bcat);
    cudaGetSymbolAddress((void**)&ABX,  g_ABX);
    cudaGetSymbolAddress((void**)&Ap,   g_Ap);
    cudaGetSymbolAddress((void**)&Bp,   g_Bp);
    cudaGetSymbolAddress((void**)&Wcat, g_Wcat);
    cudaGetSymbolAddress((void**)&lp,   g_losspart);
    {
        float* base;
        cudaGetSymbolAddress((void**)&base, g_xbuf);
        xb[0] = base; xb[1] = base + E_MAX * NL;
        cudaGetSymbolAddress((void**)&base, g_sintra);
        si[0] = base; si[1] = base + E_MAX * NL;
        cudaGetSymbolAddress((void**)&base, g_sinter);
        se[0] = base; se[1] = base + E_MAX * NL;
        cudaGetSymbolAddress((void**)&base, g_cintra);
        ci[0] = base; ci[1] = base + E_MAX;
        cudaGetSymbolAddress((void**)&base, g_cinter);
        ce[0] = base; ce[1] = base + E_MAX;
    }

    int loff = out_size - 3 * P;
    if (loff < 0) loff = 0;
    float* logits_out = out + loff;

    // 1) extract (bf16x3 rows) + W transpose/split + prep
    extract_kernel<<<E, D_DIM / 4>>>(sent, esent, estart, elen, Acat);
    wtrans_kernel<<<dim3(NBIG / 32, D_DIM / 32), dim3(32, 8)>>>(W1, Wproj, Bcat);
    {
        long tot = 3 * NL * NL + (long)E * NL + E + 4;
        prep_kernel<<<(int)((tot + 255) / 256), 256>>>(Wself, Wintra, Winter, E);
    }

    // 2) tensor-core (warp mma) big GEMM: ABX = Acat @ Bcat^T
    {
        dim3 g(NBIG / 128, (E_MAX + 127) / 128);   // 9 x 16; row guard inside
        mma_gemm<<<g, 256>>>(E, Acat, Bcat, ABX);
    }

    // 3) three iterations
    const float* W1c = W1 + (size_t)1536 * HID;
    for (int it = 0; it < 3; it++) {
        int ph = it & 1, po = ph ^ 1;
        const float* xin = (it == 0) ? (ABX + 1024) : xb[(it - 1) & 1];
        int xld = (it == 0) ? NBIG : NL;
        float* xout = xb[it & 1];

        {
            dim3 g(HID / 64, (E + 63) / 64);
            cgemm_fused<<<g, 256>>>(E, xin, xld, W1c, ABX, b1, Ap, Bp);
        }
        pair_kernel<<<(P + 7) / 8, 256>>>(Ap, Bp, xin, xld, W2, b2,
                                          pair1, pair2, rtype, targ,
                                          si[ph], se[ph], ci[ph], ce[ph],
                                          si[po], se[po], ci[po], ce[po],
                                          lp + it, (it == 2) ? logits_out : nullptr, P, E);
        {
            dim3 g(NL / 64, (E + 63) / 64);
            upd_fused<<<g, 256>>>(E, xin, xld,
                                  si[ph], se[ph], ci[ph], ce[ph],
                                  Wcat, xout);
        }
    }

    // 4) loss
    final_loss_kernel<<<1, 1>>>(lp, out, P);
}

// round 7
// speedup vs baseline: 3.3599x; 1.0512x over previous
#include <cuda_runtime.h>
#include <cuda_bf16.h>
#include <math.h>
#include <stdint.h>

#define NSENT 64
#define S_LEN 512
#define D_DIM 768
#define NL    128
#define HID   512
#define CLS   3
#define E_MAX 2000
#define P_MAX 20000
#define NBIG  1152            // 512(A0) + 512(B0) + 128(x0)
#define KCAT  2304            // 3 * 768 (bf16x3 split along K)
#define BKH   32              // K-halves per smem chunk
#define NCH   (KCAT / BKH)    // 72
#define KCC   384             // 3 * 128 (cgemm bf16x3 K)
#define NCHC  (KCC / BKH)     // 12

// ---------------- static device scratch ----------------
__device__ __nv_bfloat16 g_Acat[E_MAX * KCAT];   // [hi | lo | hi] along K
__device__ __nv_bfloat16 g_Bcat[NBIG * KCAT];    // W^T, [hi | hi | lo] along K
__device__ __nv_bfloat16 g_W1cT[HID * KCC];      // W1c^T, [hi | hi | lo]
__device__ __nv_bfloat16 g_xcat[E_MAX * KCC];    // x split [hi | lo | hi]
__device__ float g_ABX  [E_MAX * NBIG];          // [A0 | B0 | x0]
__device__ float g_Ap   [E_MAX * HID];           // A0 + C + b1
__device__ float g_Bp   [E_MAX * HID];           // B0 - C
__device__ float g_xbuf [2][E_MAX * NL];
__device__ float g_sintra[2][E_MAX * NL];
__device__ float g_sinter[2][E_MAX * NL];
__device__ float g_cintra[2][E_MAX];
__device__ float g_cinter[2][E_MAX];
__device__ float g_Wcat [3 * NL * NL];
__device__ float g_losspart[4];

// ---------------- warp-mma / cp.async helpers (portable sm_80+ ISA) -----------
__device__ __forceinline__ uint32_t smem_u32(const void* p) {
    uint32_t a;
    asm("{ .reg .u64 t; cvta.to.shared.u64 t, %1; cvt.u32.u64 %0, t; }"
        : "=r"(a) : "l"(p));
    return a;
}
__device__ __forceinline__ void ldmatrix_x4(uint32_t* r, uint32_t addr) {
    asm volatile("ldmatrix.sync.aligned.m8n8.x4.shared.b16 {%0,%1,%2,%3}, [%4];"
                 : "=r"(r[0]), "=r"(r[1]), "=r"(r[2]), "=r"(r[3]) : "r"(addr));
}
__device__ __forceinline__ void ldmatrix_x2(uint32_t* r, uint32_t addr) {
    asm volatile("ldmatrix.sync.aligned.m8n8.x2.shared.b16 {%0,%1}, [%2];"
                 : "=r"(r[0]), "=r"(r[1]) : "r"(addr));
}
__device__ __forceinline__ void mma16816(float* d, const uint32_t* a, const uint32_t* b) {
    asm volatile("mma.sync.aligned.m16n8k16.row.col.f32.bf16.bf16.f32 "
                 "{%0,%1,%2,%3}, {%4,%5,%6,%7}, {%8,%9}, {%0,%1,%2,%3};"
                 : "+f"(d[0]), "+f"(d[1]), "+f"(d[2]), "+f"(d[3])
                 : "r"(a[0]), "r"(a[1]), "r"(a[2]), "r"(a[3]), "r"(b[0]), "r"(b[1]));
}
__device__ __forceinline__ void cp16(uint32_t dst, const void* src, int sz) {
    asm volatile("cp.async.cg.shared.global [%0], [%1], 16, %2;"
                 :: "r"(dst), "l"(src), "r"(sz));
}
__device__ __forceinline__ void cp16u(uint32_t dst, const void* src) {
    asm volatile("cp.async.cg.shared.global [%0], [%1], 16;"
                 :: "r"(dst), "l"(src));
}
#define CP_COMMIT() asm volatile("cp.async.commit_group;" ::: "memory")
#define CP_WAIT1()  asm volatile("cp.async.wait_group 1;" ::: "memory")

#define AROW 80                     // 32 halves (64B) + 16B pad, conflict-free

// ---------------- event extraction -> bf16x3 split rows of Acat ---------------
__global__ void extract_kernel(const float* __restrict__ sent,
                               const int* __restrict__ esent,
                               const int* __restrict__ estart,
                               const int* __restrict__ elen,
                               __nv_bfloat16* __restrict__ Acat)
{
    int e = blockIdx.x;
    int len = elen[e] + 1;
    int st  = estart[e];
    int snt = esent[e];
    float inv = 1.0f / (float)len;
    const float4* base = (const float4*)(sent + (size_t)snt * S_LEN * D_DIM);
    int d4 = threadIdx.x;              // blockDim = 192
    float4 acc = make_float4(0.f, 0.f, 0.f, 0.f);
    for (int o = 0; o < len; o++) {
        int idx = st + o; if (idx > S_LEN - 1) idx = S_LEN - 1;
        float4 v = base[(size_t)idx * (D_DIM / 4) + d4];
        acc.x += v.x; acc.y += v.y; acc.z += v.z; acc.w += v.w;
    }
    acc.x *= inv; acc.y *= inv; acc.z *= inv; acc.w *= inv;
    float vv[4] = {acc.x, acc.y, acc.z, acc.w};
    ushort4 hi4, lo4;
    unsigned short h[4], l[4];
    #pragma unroll
    for (int j = 0; j < 4; j++) {
        __nv_bfloat16 hb = __float2bfloat16_rn(vv[j]);
        __nv_bfloat16 lb = __float2bfloat16_rn(vv[j] - __bfloat162float(hb));
        h[j] = __bfloat16_as_ushort(hb);
        l[j] = __bfloat16_as_ushort(lb);
    }
    hi4.x = h[0]; hi4.y = h[1]; hi4.z = h[2]; hi4.w = h[3];
    lo4.x = l[0]; lo4.y = l[1]; lo4.z = l[2]; lo4.w = l[3];
    ushort4* row = (ushort4*)(Acat + (size_t)e * KCAT);
    row[d4]                 = hi4;
    row[(768 / 4) + d4]     = lo4;
    row[(1536 / 4) + d4]    = hi4;
}

// ---------------- W transpose + bf16x3 split: Bcat[n][k] ----------------------
__global__ void wtrans_kernel(const float* __restrict__ W1,
                              const float* __restrict__ Wproj,
                              __nv_bfloat16* __restrict__ Bcat)
{
    __shared__ float t[32][33];
    int n0 = blockIdx.x * 32, k0 = blockIdx.y * 32;
    int tx = threadIdx.x, ty = threadIdx.y;   // block (32, 8)
    #pragma unroll
    for (int i = 0; i < 32; i += 8) {
        int k = k0 + ty + i, n = n0 + tx;
        float v;
        if (n < 512)        v = W1[(size_t)k * HID + n];
        else if (n < 1024)  v = W1[(size_t)(768 + k) * HID + (n - 512)];
        else                v = Wproj[(size_t)k * NL + (n - 1024)];
        t[ty + i][tx] = v;
    }
    __syncthreads();
    #pragma unroll
    for (int i = 0; i < 32; i += 8) {
        int n = n0 + ty + i, k = k0 + tx;
        float v = t[tx][ty + i];
        __nv_bfloat16 hb = __float2bfloat16_rn(v);
        __nv_bfloat16 lb = __float2bfloat16_rn(v - __bfloat162float(hb));
        Bcat[(size_t)n * KCAT + k]        = hb;
        Bcat[(size_t)n * KCAT + 768 + k]  = hb;
        Bcat[(size_t)n * KCAT + 1536 + k] = lb;
    }
}

// ---------------- W1c^T split (512 x 384): once -------------------------------
__global__ void wtransc_kernel(const float* __restrict__ W1c,
                               __nv_bfloat16* __restrict__ W1cT)
{
    __shared__ float t[32][33];
    int n0 = blockIdx.x * 32, k0 = blockIdx.y * 32;
    int tx = threadIdx.x, ty = threadIdx.y;   // block (32, 8)
    #pragma unroll
    for (int i = 0; i < 32; i += 8) {
        int k = k0 + ty + i, n = n0 + tx;
        t[ty + i][tx] = W1c[(size_t)k * HID + n];
    }
    __syncthreads();
    #pragma unroll
    for (int i = 0; i < 32; i += 8) {
        int n = n0 + ty + i, k = k0 + tx;
        float v = t[tx][ty + i];
        __nv_bfloat16 hb = __float2bfloat16_rn(v);
        __nv_bfloat16 lb = __float2bfloat16_rn(v - __bfloat162float(hb));
        W1cT[(size_t)n * KCC + k]        = hb;
        W1cT[(size_t)n * KCC + 128 + k]  = hb;
        W1cT[(size_t)n * KCC + 256 + k]  = lb;
    }
}

// ---------------- x split: xcat[e][0:128]=hi, [128:256]=lo, [256:384]=hi ------
__global__ void xsplit_kernel(int E_, const float* __restrict__ x, int xld,
                              __nv_bfloat16* __restrict__ xcat)
{
    int e = blockIdx.x;
    int k = threadIdx.x;    // 128
    float v = x[(size_t)e * xld + k];
    __nv_bfloat16 hb = __float2bfloat16_rn(v);
    __nv_bfloat16 lb = __float2bfloat16_rn(v - __bfloat162float(hb));
    xcat[(size_t)e * KCC + k]       = hb;
    xcat[(size_t)e * KCC + 128 + k] = lb;
    xcat[(size_t)e * KCC + 256 + k] = hb;
}

// ---------------- prep: Wcat stack + zero phase-0 + loss ----------------------
__global__ void prep_kernel(const float* __restrict__ Wself,
                            const float* __restrict__ Wintra,
                            const float* __restrict__ Winter,
                            int E)
{
    long i = (long)blockIdx.x * blockDim.x + threadIdx.x;
    const long N_WCAT = 3 * NL * NL;
    if (i < N_WCAT) {
        int k = (int)(i / NL), d = (int)(i % NL);
        const float* src = (k < NL) ? Wself : ((k < 2 * NL) ? Wintra : Winter);
        g_Wcat[i] = src[(k % NL) * NL + d];
        return;
    }
    i -= N_WCAT;
    if (i < (long)E * NL) { g_sintra[0][i] = 0.f; g_sinter[0][i] = 0.f; return; }
    i -= (long)E * NL;
    if (i < E) { g_cintra[0][i] = 0.f; g_cinter[0][i] = 0.f; return; }
    i -= E;
    if (i < 4) g_losspart[i] = 0.f;
}

// ---------------- big mma GEMM: ABX = Acat @ Bcat^T, cp.async 3-stage ---------
// grid (9, 16), 256 threads = 8 warps (2x4) of 64x32. 72 chunks of 32 halves.
#define BIG_ASTG (128 * AROW)               // 10240 B per matrix per stage
#define BIG_STG  (2 * BIG_ASTG)             // 20480 B per stage
#define BIG_SMEM (3 * BIG_STG)              // 61440 B dynamic

__global__ void __launch_bounds__(256) mma_gemm(
    int E_,
    const __nv_bfloat16* __restrict__ Acat,
    const __nv_bfloat16* __restrict__ Bcat,
    float* __restrict__ Cout)
{
    extern __shared__ char sm[];
    const int tid  = threadIdx.x;
    const int lane = tid & 31, wid = tid >> 5;
    const int wm = (wid & 1) * 64;
    const int wn = (wid >> 1) * 32;
    const int brow = blockIdx.y * 128;
    const int bcol = blockIdx.x * 128;

    float acc[4][4][4];
    #pragma unroll
    for (int mi = 0; mi < 4; mi++)
        #pragma unroll
        for (int ni = 0; ni < 4; ni++)
            #pragma unroll
            for (int r = 0; r < 4; r++) acc[mi][ni][r] = 0.f;

    auto issue = [&](int c, int s) {
        char* base = sm + s * BIG_STG;
        #pragma unroll
        for (int j = 0; j < 2; j++) {
            int ch  = tid + j * 256;           // 0..511
            int row = ch >> 2;
            int off = (ch & 3) * 16;
            int gr  = brow + row;
            int ok  = (gr < E_);
            const char* srcA = (const char*)(Acat + (size_t)(ok ? gr : 0) * KCAT
                                             + (size_t)c * BKH) + off;
            cp16(smem_u32(base + row * AROW + off), srcA, ok ? 16 : 0);
            const char* srcB = (const char*)(Bcat + (size_t)(bcol + row) * KCAT
                                             + (size_t)c * BKH) + off;
            cp16u(smem_u32(base + BIG_ASTG + row * AROW + off), srcB);
        }
        CP_COMMIT();
    };

    issue(0, 0);
    issue(1, 1);

    for (int c = 0; c < NCH; c++) {
        int s = c % 3;
        CP_WAIT1();
        __syncthreads();
        if (c + 2 < NCH) issue(c + 2, (c + 2) % 3);
        else CP_COMMIT();

        char* base = sm + s * BIG_STG;
        #pragma unroll
        for (int kk = 0; kk < 2; kk++) {
            uint32_t af[4][4], bf2[4][2];
            #pragma unroll
            for (int mi = 0; mi < 4; mi++)
                ldmatrix_x4(af[mi], smem_u32(base + (wm + mi * 16 + (lane & 15)) * AROW
                                             + (kk * 16 + (lane >> 4) * 8) * 2));
            #pragma unroll
            for (int ni = 0; ni < 4; ni++)
                ldmatrix_x2(bf2[ni], smem_u32(base + BIG_ASTG + (wn + ni * 8 + (lane & 7)) * AROW
                                              + (kk * 16 + ((lane >> 3) & 1) * 8) * 2));
            #pragma unroll
            for (int mi = 0; mi < 4; mi++)
                #pragma unroll
                for (int ni = 0; ni < 4; ni++)
                    mma16816(acc[mi][ni], af[mi], bf2[ni]);
        }
    }

    #pragma unroll
    for (int mi = 0; mi < 4; mi++) {
        int m0 = brow + wm + mi * 16 + (lane >> 2);
        #pragma unroll
        for (int ni = 0; ni < 4; ni++) {
            int n = bcol + wn + ni * 8 + (lane & 3) * 2;
            if (m0 < E_)
                *(float2*)(Cout + (size_t)m0 * NBIG + n) =
                    make_float2(acc[mi][ni][0], acc[mi][ni][1]);
            if (m0 + 8 < E_)
                *(float2*)(Cout + (size_t)(m0 + 8) * NBIG + n) =
                    make_float2(acc[mi][ni][2], acc[mi][ni][3]);
        }
    }
}

// ---------------- cgemm via mma: C = xcat@W1cT^T; epi Ap=A0+C+b1, Bp=B0-C -----
// tile 64x128, grid (4, 32), 8 warps (2x4) of 32x32, 12 chunks, 3-stage cp.async
#define CG_ASTG (64 * AROW)                 // 5120
#define CG_BSTG (128 * AROW)                // 10240
#define CG_STG  (CG_ASTG + CG_BSTG)         // 15360
// static smem: 3 * 15360 = 46080 B

__global__ void __launch_bounds__(256) cgemm_mma(
    int E_,
    const __nv_bfloat16* __restrict__ xcat,
    const __nv_bfloat16* __restrict__ W1cT,
    const float* __restrict__ ABX,
    const float* __restrict__ b1,
    float* __restrict__ Ap, float* __restrict__ Bp)
{
    __shared__ __align__(16) char sm[3 * CG_STG];
    const int tid  = threadIdx.x;
    const int lane = tid & 31, wid = tid >> 5;
    const int wm = (wid & 1) * 32;
    const int wn = (wid >> 1) * 32;
    const int brow = blockIdx.y * 64;
    const int bcol = blockIdx.x * 128;

    float acc[2][4][4];
    #pragma unroll
    for (int mi = 0; mi < 2; mi++)
        #pragma unroll
        for (int ni = 0; ni < 4; ni++)
            #pragma unroll
            for (int r = 0; r < 4; r++) acc[mi][ni][r] = 0.f;

    auto issue = [&](int c, int s) {
        char* base = sm + s * CG_STG;
        {   // A: 256 chunks
            int row = tid >> 2;
            int off = (tid & 3) * 16;
            int gr  = brow + row;
            int ok  = (gr < E_);
            const char* srcA = (const char*)(xcat + (size_t)(ok ? gr : 0) * KCC
                                             + (size_t)c * BKH) + off;
            cp16(smem_u32(base + row * AROW + off), srcA, ok ? 16 : 0);
        }
        #pragma unroll
        for (int j = 0; j < 2; j++) {      // B: 512 chunks
            int ch  = tid + j * 256;
            int row = ch >> 2;
            int off = (ch & 3) * 16;
            const char* srcB = (const char*)(W1cT + (size_t)(bcol + row) * KCC
                                             + (size_t)c * BKH) + off;
            cp16u(smem_u32(base + CG_ASTG + row * AROW + off), srcB);
        }
        CP_COMMIT();
    };

    issue(0, 0);
    issue(1, 1);

    for (int c = 0; c < NCHC; c++) {
        int s = c % 3;
        CP_WAIT1();
        __syncthreads();
        if (c + 2 < NCHC) issue(c + 2, (c + 2) % 3);
        else CP_COMMIT();

        char* base = sm + s * CG_STG;
        #pragma unroll
        for (int kk = 0; kk < 2; kk++) {
            uint32_t af[2][4], bf2[4][2];
            #pragma unroll
            for (int mi = 0; mi < 2; mi++)
                ldmatrix_x4(af[mi], smem_u32(base + (wm + mi * 16 + (lane & 15)) * AROW
                                             + (kk * 16 + (lane >> 4) * 8) * 2));
            #pragma unroll
            for (int ni = 0; ni < 4; ni++)
                ldmatrix_x2(bf2[ni], smem_u32(base + CG_ASTG + (wn + ni * 8 + (lane & 7)) * AROW
                                              + (kk * 16 + ((lane >> 3) & 1) * 8) * 2));
            #pragma unroll
            for (int mi = 0; mi < 2; mi++)
                #pragma unroll
                for (int ni = 0; ni < 4; ni++)
                    mma16816(acc[mi][ni], af[mi], bf2[ni]);
        }
    }

    // epilogue: Ap = A0 + C + b1, Bp = B0 - C
    #pragma unroll
    for (int mi = 0; mi < 2; mi++) {
        int m0 = brow + wm + mi * 16 + (lane >> 2);
        #pragma unroll
        for (int ni = 0; ni < 4; ni++) {
            int n = bcol + wn + ni * 8 + (lane & 3) * 2;
            float2 b1v = *(const float2*)(b1 + n);
            #pragma unroll
            for (int half = 0; half < 2; half++) {
                int r = m0 + half * 8;
                if (r >= E_) continue;
                float c0 = acc[mi][ni][half * 2 + 0];
                float c1 = acc[mi][ni][half * 2 + 1];
                float2 a0v = *(const float2*)(ABX + (size_t)r * NBIG + n);
                float2 b0v = *(const float2*)(ABX + (size_t)r * NBIG + 512 + n);
                *(float2*)(Ap + (size_t)r * HID + n) =
                    make_float2(a0v.x + c0 + b1v.x, a0v.y + c1 + b1v.y);
                *(float2*)(Bp + (size_t)r * HID + n) =
                    make_float2(b0v.x - c0, b0v.y - c1);
            }
        }
    }
}

// ---------------- fused update GEMM: x_out = relu(Z@Wcat), Z built on the fly -
__device__ __forceinline__ float4 z_load(
    const float* __restrict__ xin, int xld,
    const float* __restrict__ sintra, const float* __restrict__ sinter,
    const float* __restrict__ cintra, const float* __restrict__ cinter,
    int r, int kg)
{
    int seg = kg >> 7, d = kg & 127;
    if (seg == 0) {
        return *(const float4*)(xin + (size_t)r * xld + d);
    } else if (seg == 1) {
        float4 s = *(const float4*)(sintra + (size_t)r * NL + d);
        float4 xv = *(const float4*)(xin + (size_t)r * xld + d);
        float rc = 0.7f / (cintra[r] + 1.0f);
        return make_float4((s.x + xv.x) * rc, (s.y + xv.y) * rc,
                           (s.z + xv.z) * rc, (s.w + xv.w) * rc);
    } else {
        float4 s = *(const float4*)(sinter + (size_t)r * NL + d);
        float rc = 0.3f / fmaxf(cinter[r], 1.0f);
        return make_float4(s.x * rc, s.y * rc, s.z * rc, s.w * rc);
    }
}

__global__ void __launch_bounds__(256) upd_fused(
    int M,
    const float* __restrict__ xin, int xld,
    const float* __restrict__ sintra, const float* __restrict__ sinter,
    const float* __restrict__ cintra, const float* __restrict__ cinter,
    const float* __restrict__ Wcat,
    float* __restrict__ xout)
{
    const int BM = 64, BN = 64, BK = 16, KTOT = 3 * NL;
    __shared__ float As[2][BK][BM];
    __shared__ float Bs[2][BK][BN];
    const int tid  = threadIdx.x;
    const int brow = blockIdx.y * BM;
    const int bcol = blockIdx.x * BN;
    const int ar = tid >> 2, ac = (tid & 3) * 4;
    const int br = tid >> 4, bc = (tid & 15) * 4;
    const int tx = tid & 15, ty = tid >> 4;

    float4 areg = make_float4(0.f,0.f,0.f,0.f), breg;
    if (brow + ar < M) areg = z_load(xin, xld, sintra, sinter, cintra, cinter, brow + ar, ac);
    breg = *(const float4*)(Wcat + (size_t)br * NL + bcol + bc);
    As[0][ac+0][ar] = areg.x; As[0][ac+1][ar] = areg.y; As[0][ac+2][ar] = areg.z; As[0][ac+3][ar] = areg.w;
    *(float4*)&Bs[0][br][bc] = breg;
    __syncthreads();

    float acc[4][4];
    #pragma unroll
    for (int i = 0; i < 4; i++)
        #pragma unroll
        for (int j = 0; j < 4; j++) acc[i][j] = 0.f;

    int buf = 0;
    for (int k0 = BK; k0 < KTOT; k0 += BK) {
        areg = make_float4(0.f,0.f,0.f,0.f);
        if (brow + ar < M) areg = z_load(xin, xld, sintra, sinter, cintra, cinter, brow + ar, k0 + ac);
        breg = *(const float4*)(Wcat + (size_t)(k0 + br) * NL + bcol + bc);
        #pragma unroll
        for (int k = 0; k < BK; k++) {
            float av[4], bv[4];
            *(float4*)av = *(const float4*)&As[buf][k][ty * 4];
            *(float4*)bv = *(const float4*)&Bs[buf][k][tx * 4];
            #pragma unroll
            for (int i = 0; i < 4; i++)
                #pragma unroll
                for (int j = 0; j < 4; j++)
                    acc[i][j] = fmaf(av[i], bv[j], acc[i][j]);
        }
        int nb = buf ^ 1;
        As[nb][ac+0][ar] = areg.x; As[nb][ac+1][ar] = areg.y; As[nb][ac+2][ar] = areg.z; As[nb][ac+3][ar] = areg.w;
        *(float4*)&Bs[nb][br][bc] = breg;
        __syncthreads();
        buf = nb;
    }
    #pragma unroll
    for (int k = 0; k < BK; k++) {
        float av[4], bv[4];
        *(float4*)av = *(const float4*)&As[buf][k][ty * 4];
        *(float4*)bv = *(const float4*)&Bs[buf][k][tx * 4];
        #pragma unroll
        for (int i = 0; i < 4; i++)
            #pragma unroll
            for (int j = 0; j < 4; j++)
                acc[i][j] = fmaf(av[i], bv[j], acc[i][j]);
    }

    #pragma unroll
    for (int i = 0; i < 4; i++) {
        int r = brow + ty * 4 + i;
        if (r >= M) continue;
        float4 o;
        o.x = fmaxf(acc[i][0], 0.f); o.y = fmaxf(acc[i][1], 0.f);
        o.z = fmaxf(acc[i][2], 0.f); o.w = fmaxf(acc[i][3], 0.f);
        *(float4*)(xout + (size_t)r * NL + bcol + tx * 4) = o;
    }
}

// ---------------- per-pair: logits, CE, masks, scatter; zero other phase ------
__global__ void __launch_bounds__(256) pair_kernel(
    const float* __restrict__ Ap, const float* __restrict__ Bp,
    const float* __restrict__ xin, int xld,
    const float* __restrict__ W2, const float* __restrict__ b2,
    const int* __restrict__ pair1, const int* __restrict__ pair2,
    const int* __restrict__ rtype, const int* __restrict__ targ,
    float* sintra, float* sinter, float* cintra, float* cinter,
    float* si_o, float* se_o, float* ci_o, float* ce_o,
    float* lossacc, float* logits_out, int P, int E)
{
    __shared__ float W2s0[HID], W2s1[HID], W2s2[HID];
    __shared__ float b2s[CLS];
    __shared__ float ce_s[8];
    int tid = threadIdx.x;
    for (int i = tid; i < HID; i += 256) {
        W2s0[i] = W2[i * 3 + 0];
        W2s1[i] = W2[i * 3 + 1];
        W2s2[i] = W2[i * 3 + 2];
    }
    if (tid < CLS) b2s[tid] = b2[tid];

    {
        long idx = (long)blockIdx.x * 256 + tid;
        long stride = (long)gridDim.x * 256;
        for (long i = idx; i < (long)E * NL; i += stride) { si_o[i] = 0.f; se_o[i] = 0.f; }
        for (long i = idx; i < E; i += stride) { ci_o[i] = 0.f; ce_o[i] = 0.f; }
    }
    __syncthreads();

    int warp = tid >> 5, lane = tid & 31;
    int p = blockIdx.x * 8 + warp;
    float ce = 0.f;
    if (p < P) {
        int p1 = pair1[p], p2 = pair2[p];
        const float4* a4 = (const float4*)(Ap + (size_t)p1 * HID);
        const float4* b4 = (const float4*)(Bp + (size_t)p2 * HID);
        float a0 = 0.f, a1 = 0.f, a2 = 0.f;
        #pragma unroll
        for (int j = 0; j < 4; j++) {
            int i4 = j * 32 + lane;
            float4 av = a4[i4], bv = b4[i4];
            float4 h;
            h.x = fmaxf(av.x + bv.x, 0.f);
            h.y = fmaxf(av.y + bv.y, 0.f);
            h.z = fmaxf(av.z + bv.z, 0.f);
            h.w = fmaxf(av.w + bv.w, 0.f);
            int base = i4 * 4;
            float4 w0 = *(const float4*)&W2s0[base];
            float4 w1 = *(const float4*)&W2s1[base];
            float4 w2 = *(const float4*)&W2s2[base];
            a0 = fmaf(h.x, w0.x, fmaf(h.y, w0.y, fmaf(h.z, w0.z, fmaf(h.w, w0.w, a0))));
            a1 = fmaf(h.x, w1.x, fmaf(h.y, w1.y, fmaf(h.z, w1.z, fmaf(h.w, w1.w, a1))));
            a2 = fmaf(h.x, w2.x, fmaf(h.y, w2.y, fmaf(h.z, w2.z, fmaf(h.w, w2.w, a2))));
        }
        #pragma unroll
        for (int o = 16; o; o >>= 1) {
            a0 += __shfl_xor_sync(0xffffffffu, a0, o);
            a1 += __shfl_xor_sync(0xffffffffu, a1, o);
            a2 += __shfl_xor_sync(0xffffffffu, a2, o);
        }
        float l0 = a0 + b2s[0], l1 = a1 + b2s[1], l2 = a2 + b2s[2];
        float m = fmaxf(l0, fmaxf(l1, l2));
        float s = expf(l0 - m) + expf(l1 - m) + expf(l2 - m);
        int tg = targ[p];
        float lt = (tg == 0) ? l0 : ((tg == 1) ? l1 : l2);
        ce = logf(s) + m - lt;
        if (logits_out != nullptr && lane == 0) {
            logits_out[(size_t)p * 3 + 0] = l0;
            logits_out[(size_t)p * 3 + 1] = l1;
            logits_out[(size_t)p * 3 + 2] = l2;
        }
        int argm = 0; float mm = l0;
        if (l1 > mm) { mm = l1; argm = 1; }
        if (l2 > mm) { mm = l2; argm = 2; }
        bool conf = (1.0f / s) > 0.3f;
        int rt = rtype[p];
        if (conf && (argm == 1 || argm == 2)) {
            bool srcIs1 = (argm == 1);
            int src = srcIs1 ? p1 : p2;
            int dst = srcIs1 ? p2 : p1;
            float* sb = (rt == 0) ? sintra : sinter;
            float* cb = (rt == 0) ? cintra : cinter;
            const float* xs = xin + (size_t)src * xld;
            #pragma unroll
            for (int j = 0; j < NL / 32; j++) {
                int d = j * 32 + lane;
                atomicAdd(&sb[(size_t)dst * NL + d], xs[d]);
            }
            if (lane == 0) atomicAdd(&cb[dst], 1.0f);
        }
    }
    if (lane == 0) ce_s[warp] = (p < P) ? ce : 0.f;
    __syncthreads();
    if (tid == 0) {
        float t = ce_s[0] + ce_s[1] + ce_s[2] + ce_s[3]
                + ce_s[4] + ce_s[5] + ce_s[6] + ce_s[7];
        atomicAdd(lossacc, t);
    }
}

__global__ void final_loss_kernel(const float* lp, float* out, int P)
{
    out[0] = (lp[0] + lp[1] * 0.5f + lp[2] * (1.0f / 3.0f)) / (float)P;
}

// ---------------- launch ------------------------------------------------------
extern "C" void kernel_launch(void* const* d_in, const int* in_sizes, int n_in,
                              void* d_out, int out_size)
{
    const float* sent   = (const float*)d_in[0];
    const float* Wproj  = (const float*)d_in[1];
    const float* W1     = (const float*)d_in[2];
    const float* b1     = (const float*)d_in[3];
    const float* W2     = (const float*)d_in[4];
    const float* b2     = (const float*)d_in[5];
    const float* Wself  = (const float*)d_in[6];
    const float* Wintra = (const float*)d_in[7];
    const float* Winter = (const float*)d_in[8];
    const int* esent  = (const int*)d_in[9];
    const int* estart = (const int*)d_in[10];
    const int* elen   = (const int*)d_in[11];
    const int* pair1  = (const int*)d_in[12];
    const int* pair2  = (const int*)d_in[13];
    const int* rtype  = (const int*)d_in[14];
    const int* targ   = (const int*)d_in[15];
    float* out = (float*)d_out;

    int E = in_sizes[9];
    int P = in_sizes[12];
    if (E > E_MAX) E = E_MAX;
    if (P > P_MAX) P = P_MAX;

    __nv_bfloat16 *Acat, *Bcat, *W1cT, *xcat;
    float *ABX, *Ap, *Bp, *Wcat, *lp;
    float *xb[2], *si[2], *se[2], *ci[2], *ce[2];
    cudaGetSymbolAddress((void**)&Acat, g_Acat);
    cudaGetSymbolAddress((void**)&Bcat, g_Bcat);
    cudaGetSymbolAddress((void**)&W1cT, g_W1cT);
    cudaGetSymbolAddress((void**)&xcat, g_xcat);
    cudaGetSymbolAddress((void**)&ABX,  g_ABX);
    cudaGetSymbolAddress((void**)&Ap,   g_Ap);
    cudaGetSymbolAddress((void**)&Bp,   g_Bp);
    cudaGetSymbolAddress((void**)&Wcat, g_Wcat);
    cudaGetSymbolAddress((void**)&lp,   g_losspart);
    {
        float* base;
        cudaGetSymbolAddress((void**)&base, g_xbuf);
        xb[0] = base; xb[1] = base + E_MAX * NL;
        cudaGetSymbolAddress((void**)&base, g_sintra);
        si[0] = base; si[1] = base + E_MAX * NL;
        cudaGetSymbolAddress((void**)&base, g_sinter);
        se[0] = base; se[1] = base + E_MAX * NL;
        cudaGetSymbolAddress((void**)&base, g_cintra);
        ci[0] = base; ci[1] = base + E_MAX;
        cudaGetSymbolAddress((void**)&base, g_cinter);
        ce[0] = base; ce[1] = base + E_MAX;
    }

    int loff = out_size - 3 * P;
    if (loff < 0) loff = 0;
    float* logits_out = out + loff;

    // 1) extract (bf16x3 rows) + W transpose/split + prep
    extract_kernel<<<E, D_DIM / 4>>>(sent, esent, estart, elen, Acat);
    wtrans_kernel<<<dim3(NBIG / 32, D_DIM / 32), dim3(32, 8)>>>(W1, Wproj, Bcat);
    wtransc_kernel<<<dim3(HID / 32, NL / 32), dim3(32, 8)>>>(W1 + (size_t)1536 * HID, W1cT);
    {
        long tot = 3 * NL * NL + (long)E * NL + E + 4;
        prep_kernel<<<(int)((tot + 255) / 256), 256>>>(Wself, Wintra, Winter, E);
    }

    // 2) tensor-core big GEMM: ABX = Acat @ Bcat^T
    cudaFuncSetAttribute(mma_gemm, cudaFuncAttributeMaxDynamicSharedMemorySize, BIG_SMEM);
    {
        dim3 g(NBIG / 128, (E_MAX + 127) / 128);   // 9 x 16; row guard inside
        mma_gemm<<<g, 256, BIG_SMEM>>>(E, Acat, Bcat, ABX);
    }

    // 3) three iterations
    for (int it = 0; it < 3; it++) {
        int ph = it & 1, po = ph ^ 1;
        const float* xin = (it == 0) ? (ABX + 1024) : xb[(it - 1) & 1];
        int xld = (it == 0) ? NBIG : NL;
        float* xout = xb[it & 1];

        xsplit_kernel<<<E, NL>>>(E, xin, xld, xcat);
        {
            dim3 g(HID / 128, (E + 63) / 64);     // 4 x 32
            cgemm_mma<<<g, 256>>>(E, xcat, W1cT, ABX, b1, Ap, Bp);
        }
        pair_kernel<<<(P + 7) / 8, 256>>>(Ap, Bp, xin, xld, W2, b2,
                                          pair1, pair2, rtype, targ,
                                          si[ph], se[ph], ci[ph], ce[ph],
                                          si[po], se[po], ci[po], ce[po],
                                          lp + it, (it == 2) ? logits_out : nullptr, P, E);
        {
            dim3 g(NL / 64, (E + 63) / 64);
            upd_fused<<<g, 256>>>(E, xin, xld,
                                  si[ph], se[ph], ci[ph], ce[ph],
                                  Wcat, xout);
        }
    }

    // 4) loss
    final_loss_kernel<<<1, 1>>>(lp, out, P);
}